// round 8
// baseline (speedup 1.0000x reference)
#include <cuda_runtime.h>
#include <cstdint>

#define DD 128
#define EPB 128          // edges (or nodes) per block

__device__ float g_agg[50000 * 128];
__device__ int g_is64;
__device__ float g_wimg[28 * 4096];  // K=32 fragment-layout tf32 weight chunk images
// 0-7: We1, 8-11: We2, 12-15: Wc1, 16-23: Wn1, 24-27: Wn2

// ---------------- helpers ----------------
__device__ __forceinline__ uint32_t smem_u32(const void* p) {
    uint32_t a;
    asm("{ .reg .u64 t; cvta.to.shared.u64 t, %1; cvt.u32.u64 %0, t; }" : "=r"(a) : "l"(p));
    return a;
}
__device__ __forceinline__ float silu_f(float x) { return __fdividef(x, 1.0f + __expf(-x)); }
__device__ __forceinline__ float tf32r(float x) {
    uint32_t o;
    asm("cvt.rna.tf32.f32 %0, %1;" : "=r"(o) : "f"(x));
    return __uint_as_float(o);
}
__device__ __forceinline__ uint4 lds128(uint32_t a) {
    uint4 v;
    asm volatile("ld.shared.v4.b32 {%0,%1,%2,%3}, [%4];"
                 : "=r"(v.x), "=r"(v.y), "=r"(v.z), "=r"(v.w) : "r"(a));
    return v;
}
__device__ __forceinline__ void mma8(float* c, uint4 a, uint32_t b0, uint32_t b1) {
    asm volatile(
        "mma.sync.aligned.m16n8k8.row.col.f32.tf32.tf32.f32 "
        "{%0,%1,%2,%3}, {%4,%5,%6,%7}, {%8,%9}, {%0,%1,%2,%3};"
        : "+f"(c[0]), "+f"(c[1]), "+f"(c[2]), "+f"(c[3])
        : "r"(a.x), "r"(a.y), "r"(a.z), "r"(a.w), "r"(b0), "r"(b1));
}
#define CP_ASYNC_4(dst, src) \
    asm volatile("cp.async.ca.shared.global [%0], [%1], 4;" :: "r"(dst), "l"(src) : "memory")
#define CP_ASYNC_16(dst, src) \
    asm volatile("cp.async.cg.shared.global [%0], [%1], 16;" :: "r"(dst), "l"(src) : "memory")
#define CP_COMMIT() asm volatile("cp.async.commit_group;" ::: "memory")
#define CP_WAIT(n)  asm volatile("cp.async.wait_group %0;" :: "n"(n) : "memory")

// ---------------- smem maps (bytes) ----------------
// Edge: X region 64KB (layer1: two 16KB K=32 chunk ring; layers 2/3: full kstot=16 layout),
//       W ring 2x16KB, tables.
#define XB_B    0
#define WB_B    65536
#define SROW_B  98304
#define SCOL_B  98816
#define SDX_B   99328
#define SDY_B   99840
#define SDZ_B   100352
#define SID_B   100864
#define SDIST_B 101376
#define W257_B  101888
#define SWC2_B  102400
#define SBE1_B  102912
#define SBE2_B  103424
#define SBC1_B  103936
#define EDGE_SMEM_BYTES 104448

#define NBN1_B  98304
#define NBN2_B  98816
#define NODE_SMEM_BYTES 99328

// ---------------- small kernels ----------------
__global__ void egnn_detect_kernel(const int* __restrict__ ei32) {
    int is64 = 1;
#pragma unroll
    for (int i = 1; i < 64; i += 2)
        if (ei32[i] != 0) is64 = 0;
    g_is64 = is64;
}

__global__ void egnn_init_kernel(const float* __restrict__ pos,
                                 float* __restrict__ pos_out,
                                 long long nAgg, long long nPos) {
    long long i = (long long)blockIdx.x * blockDim.x + threadIdx.x;
    if (i < nAgg) g_agg[i] = 0.0f;
    if (i < nPos) pos_out[i] = pos[i];
}

// Build K=32 fragment-layout tf32 weight images.
// r within image: frag=r>>7 (0..31), lane=(r>>2)&31, reg=r&3.
// nt=frag>>1, kp=frag&1; n = nt*8 + (lane>>2); kl = kp*16 + (reg>>1)*8 + (reg&1)*4 + (lane&3).
__global__ void egnn_prep_kernel(const float* __restrict__ We1,
                                 const float* __restrict__ We2,
                                 const float* __restrict__ Wc1,
                                 const float* __restrict__ Wn1,
                                 const float* __restrict__ Wn2) {
    int i = blockIdx.x * 256 + threadIdx.x;
    if (i >= 28 * 4096) return;
    int ci = i >> 12;
    int r = i & 4095;
    int frag = r >> 7;
    int lane = (r >> 2) & 31;
    int reg = r & 3;
    int nt = frag >> 1, kp = frag & 1;
    int n = nt * 8 + (lane >> 2);
    int kl = kp * 16 + (reg >> 1) * 8 + (reg & 1) * 4 + (lane & 3);
    const float* W; int kg;
    if (ci < 8)       { W = We1; kg = ci * 32 + kl; }
    else if (ci < 12) { W = We2; kg = (ci - 8) * 32 + kl; }
    else if (ci < 16) { W = Wc1; kg = (ci - 12) * 32 + kl; }
    else if (ci < 24) { W = Wn1; kg = (ci - 16) * 32 + kl; }
    else              { W = Wn2; kg = (ci - 24) * 32 + kl; }
    g_wimg[i] = tf32r(W[kg * DD + n]);
}

// ---------------- mma core ----------------
// One K=32 chunk: 2 kp steps, 16 n-tiles, 2 m-tiles per warp.
__device__ __forceinline__ void mma_chunk32(float (&C)[2][16][4], uint32_t xbase_u, uint32_t wbase_u,
                                            int mtg0, int ks0, int kstot, int lane) {
#pragma unroll
    for (int kp = 0; kp < 2; kp++) {
        int ks = ks0 + kp * 2;
        uint4 a00 = lds128(xbase_u + (uint32_t)((((mtg0 + 0) * kstot + ks) << 9) + lane * 16));
        uint4 a01 = lds128(xbase_u + (uint32_t)((((mtg0 + 0) * kstot + ks + 1) << 9) + lane * 16));
        uint4 a10 = lds128(xbase_u + (uint32_t)((((mtg0 + 1) * kstot + ks) << 9) + lane * 16));
        uint4 a11 = lds128(xbase_u + (uint32_t)((((mtg0 + 1) * kstot + ks + 1) << 9) + lane * 16));
#pragma unroll
        for (int nt = 0; nt < 16; nt++) {
            uint4 b = lds128(wbase_u + (uint32_t)(((nt * 2 + kp) << 9) + lane * 16));
            mma8(C[0][nt], a00, b.x, b.y);
            mma8(C[0][nt], a01, b.z, b.w);
            mma8(C[1][nt], a10, b.x, b.y);
            mma8(C[1][nt], a11, b.z, b.w);
        }
    }
}

// Stage one 16KB weight chunk (async), 128 threads.
__device__ __forceinline__ void stageW_async(uint32_t wbuf_u, const float* __restrict__ img, int t) {
#pragma unroll
    for (int i = 0; i < 8; i++)
        CP_ASYNC_16(wbuf_u + (uint32_t)((i * 128 + t) * 16), (const char*)(img + (i * 128 + t) * 4));
}

// Async gather of one K=32 X chunk into chunk fragment layout (kstot=4), per-warp 32 edges.
__device__ __forceinline__ void gather_chunk_async(uint32_t dstbase_u, int c, int w, int lane,
                                                   const float* __restrict__ h,
                                                   const int* srow, const int* scol) {
    const int rsel = lane >> 3;
    const int radd = (rsel & 1) + 8 * (rsel >> 1);
    const uint32_t dfix = (uint32_t)((lane & 3) * 16 + ((lane & 7) >> 2) * 8);
#pragma unroll
    for (int egrp = 0; egrp < 8; egrp++) {
        int mtl = egrp >> 2;
        int b2 = (egrp & 3) * 2;
        int r = b2 + radd;
        int ew = w * 32 + mtl * 16 + r;
        int node = (c < 4) ? srow[ew] : scol[ew];
        const char* src = (const char*)(h + (long long)node * DD + (c & 3) * 32 + (lane & 7));
        uint32_t dst = dstbase_u + (uint32_t)((ew >> 4) * 2048 + (r & 7) * 64 + (r >> 3) * 4) + dfix;
#pragma unroll
        for (int kblk = 0; kblk < 4; kblk++) {
            CP_ASYNC_4(dst, src);
            dst += 512;
            src += 32;
        }
    }
}

// Node gather: rows contiguous (n0 + ew), clamped; base = h or g_agg with feat offset.
__device__ __forceinline__ void gather_node_async(uint32_t dstbase_u, const float* __restrict__ base,
                                                  long long n0, long long Nn, int w, int lane) {
    const int rsel = lane >> 3;
    const int radd = (rsel & 1) + 8 * (rsel >> 1);
    const uint32_t dfix = (uint32_t)((lane & 3) * 16 + ((lane & 7) >> 2) * 8);
#pragma unroll
    for (int egrp = 0; egrp < 8; egrp++) {
        int mtl = egrp >> 2;
        int b2 = (egrp & 3) * 2;
        int r = b2 + radd;
        int ew = w * 32 + mtl * 16 + r;
        long long n = n0 + ew;
        if (n >= Nn) n = Nn - 1;
        const char* src = (const char*)(base + n * DD + (lane & 7));
        uint32_t dst = dstbase_u + (uint32_t)((ew >> 4) * 2048 + (r & 7) * 64 + (r >> 3) * 4) + dfix;
#pragma unroll
        for (int kblk = 0; kblk < 4; kblk++) {
            CP_ASYNC_4(dst, src);
            dst += 512;
            src += 32;
        }
    }
}

#define CLEAR_C() \
    _Pragma("unroll") for (int mt = 0; mt < 2; mt++) \
    _Pragma("unroll") for (int nt = 0; nt < 16; nt++) \
    _Pragma("unroll") for (int q = 0; q < 4; q++) C[mt][nt][q] = 0.0f

// ================= edge kernel =================
__global__ __launch_bounds__(128, 2) void egnn_edge_mma(
    const float* __restrict__ h, const float* __restrict__ pos,
    const int* __restrict__ ei32, long long E,
    const float* __restrict__ We1, const float* __restrict__ be1,
    const float* __restrict__ be2, const float* __restrict__ bc1,
    const float* __restrict__ Wc2, float* __restrict__ pos_out)
{
    extern __shared__ __align__(16) float smem[];
    char* sb = (char*)smem;
    const uint32_t sbase = smem_u32(smem);
    float* xbf   = (float*)(sb + XB_B);
    int*   srow  = (int*)(sb + SROW_B);
    int*   scol  = (int*)(sb + SCOL_B);
    float* sdx   = (float*)(sb + SDX_B);
    float* sdy   = (float*)(sb + SDY_B);
    float* sdz   = (float*)(sb + SDZ_B);
    float* sid   = (float*)(sb + SID_B);
    float* sdist = (float*)(sb + SDIST_B);
    float* w257s = (float*)(sb + W257_B);
    float* swc2  = (float*)(sb + SWC2_B);
    float* sbe1  = (float*)(sb + SBE1_B);
    float* sbe2  = (float*)(sb + SBE2_B);
    float* sbc1  = (float*)(sb + SBC1_B);

    const int t = threadIdx.x;
    const int w = t >> 5;
    const int lane = t & 31;
    const int g = lane >> 2;
    const int tig = lane & 3;
    const long long e0 = (long long)blockIdx.x * EPB;

    // setup: edge meta + tables (128 threads -> one edge each)
    {
        long long e = e0 + t;
        if (e >= E) e = E - 1;
        int r, c;
        if (g_is64) { r = ei32[2 * e]; c = ei32[2 * (E + e)]; }
        else        { r = ei32[e];     c = ei32[E + e]; }
        srow[t] = r; scol[t] = c;
        float dx = pos[r * 3 + 0] - pos[c * 3 + 0];
        float dy = pos[r * 3 + 1] - pos[c * 3 + 1];
        float dz = pos[r * 3 + 2] - pos[c * 3 + 2];
        float d = sqrtf(dx * dx + dy * dy + dz * dz);
        d = fmaxf(d, 1e-6f);
        sdx[t] = dx; sdy[t] = dy; sdz[t] = dz;
        sid[t] = 1.0f / d; sdist[t] = d;
        w257s[t] = We1[256 * DD + t];   // dist row kept fp32 (rank-1)
        swc2[t]  = Wc2[t];
        sbe1[t]  = be1[t];
        sbe2[t]  = be2[t];
        sbc1[t]  = bc1[t];
    }
    __syncthreads();

    float C[2][16][4];
    const uint32_t xb0 = sbase + XB_B;
    const uint32_t wb0 = sbase + WB_B;
    const int mtg0 = 2 * w;

    // ---------- layer 1: K=256, 8 pipelined K=32 chunks ----------
    CLEAR_C();
    stageW_async(wb0, g_wimg + 0 * 4096, t);
    gather_chunk_async(xb0, 0, w, lane, h, srow, scol);
    CP_COMMIT();
    for (int c = 0; c < 8; c++) {
        if (c > 0) __syncthreads();          // mma(c-1) done -> its buffers reusable
        if (c < 7) {
            int b = (c + 1) & 1;
            stageW_async(wb0 + b * 16384, g_wimg + (c + 1) * 4096, t);
            gather_chunk_async(xb0 + b * 16384, c + 1, w, lane, h, srow, scol);
            CP_COMMIT();
            CP_WAIT(1);
        } else CP_WAIT(0);
        __syncthreads();
        int b = c & 1;
        mma_chunk32(C, xb0 + b * 16384, wb0 + b * 16384, mtg0, 0, 4, lane);
    }
    __syncthreads();

    // stage layer-2 chunk 0 during epilogue
    stageW_async(wb0, g_wimg + 8 * 4096, t);
    CP_COMMIT();

    // epilogue 1: + dist*w257 + be1, silu, tf32 -> X2 full layout (kstot=16)
#pragma unroll
    for (int mt = 0; mt < 2; mt++)
#pragma unroll
        for (int nt = 0; nt < 16; nt++)
#pragma unroll
            for (int q = 0; q < 4; q++) {
                int n = nt * 8 + 2 * tig + (q & 1);
                int r = g + 8 * (q >> 1);
                int ew = w * 32 + mt * 16 + r;
                float v = C[mt][nt][q] + sdist[ew] * w257s[n] + sbe1[n];
                v = tf32r(silu_f(v));
                int frag = (ew >> 4) * 16 + nt;
                int ls = (r & 7) * 4 + (n & 3);
                int rg = (r >> 3) + 2 * ((n & 7) >> 2);
                xbf[frag * 128 + ls * 4 + rg] = v;
            }
    __syncthreads();

    // ---------- layer 2: K=128, 4 chunks on resident X2 ----------
    CLEAR_C();
    for (int c = 0; c < 4; c++) {
        if (c > 0) __syncthreads();
        if (c < 3) {
            stageW_async(wb0 + ((c + 1) & 1) * 16384, g_wimg + (8 + c + 1) * 4096, t);
            CP_COMMIT();
            CP_WAIT(1);
        } else CP_WAIT(0);
        __syncthreads();
        mma_chunk32(C, xb0, wb0 + (c & 1) * 16384, mtg0, 4 * c, 16, lane);
    }
    __syncthreads();

    stageW_async(wb0, g_wimg + 12 * 4096, t);
    CP_COMMIT();

    // epilogue 2: msg = silu(C + be2), tf32 -> X3 (overwrite X2)
#pragma unroll
    for (int mt = 0; mt < 2; mt++)
#pragma unroll
        for (int nt = 0; nt < 16; nt++)
#pragma unroll
            for (int q = 0; q < 4; q++) {
                int n = nt * 8 + 2 * tig + (q & 1);
                int r = g + 8 * (q >> 1);
                int ew = w * 32 + mt * 16 + r;
                float v = tf32r(silu_f(C[mt][nt][q] + sbe2[n]));
                int frag = (ew >> 4) * 16 + nt;
                int ls = (r & 7) * 4 + (n & 3);
                int rg = (r >> 3) + 2 * ((n & 7) >> 2);
                xbf[frag * 128 + ls * 4 + rg] = v;
            }
    __syncthreads();

    // ---------- layer 3: K=128, 4 chunks ----------
    CLEAR_C();
    for (int c = 0; c < 4; c++) {
        if (c > 0) __syncthreads();
        if (c < 3) {
            stageW_async(wb0 + ((c + 1) & 1) * 16384, g_wimg + (12 + c + 1) * 4096, t);
            CP_COMMIT();
            CP_WAIT(1);
        } else CP_WAIT(0);
        __syncthreads();
        mma_chunk32(C, xb0, wb0 + (c & 1) * 16384, mtg0, 4 * c, 16, lane);
    }

    // agg scatter from X3 (coalesced atomics across j)
    {
        int j = t;
#pragma unroll 4
        for (int el = 0; el < 128; el++) {
            if (e0 + el < E) {
                int r = el & 15;
                int frag = (el >> 4) * 16 + (j >> 3);
                int ls = (r & 7) * 4 + (j & 3);
                int rg = (r >> 3) + 2 * ((j & 7) >> 2);
                float m = xbf[frag * 128 + ls * 4 + rg];
                atomicAdd(&g_agg[(long long)srow[el] * DD + j], m);
            }
        }
    }

    // coord epilogue: clip(sum_n silu(C + bc1)*wc2) -> pos atomics
    {
        float sp[2][2] = {{0.f, 0.f}, {0.f, 0.f}};
#pragma unroll
        for (int mt = 0; mt < 2; mt++)
#pragma unroll
            for (int nt = 0; nt < 16; nt++)
#pragma unroll
                for (int q = 0; q < 4; q++) {
                    int n = nt * 8 + 2 * tig + (q & 1);
                    sp[mt][q >> 1] += silu_f(C[mt][nt][q] + sbc1[n]) * swc2[n];
                }
#pragma unroll
        for (int mt = 0; mt < 2; mt++)
#pragma unroll
            for (int hb = 0; hb < 2; hb++) {
                float s = sp[mt][hb];
                s += __shfl_xor_sync(0xFFFFFFFFu, s, 1);
                s += __shfl_xor_sync(0xFFFFFFFFu, s, 2);
                sp[mt][hb] = s;
            }
        if (tig == 0) {
#pragma unroll
            for (int mt = 0; mt < 2; mt++)
#pragma unroll
                for (int hb = 0; hb < 2; hb++) {
                    int ew = w * 32 + mt * 16 + g + 8 * hb;
                    if (e0 + ew < E) {
                        float s = fminf(fmaxf(sp[mt][hb], -1.0f), 1.0f);
                        float fac = s * sid[ew];
                        long long rr = srow[ew];
                        atomicAdd(&pos_out[rr * 3 + 0], sdx[ew] * fac);
                        atomicAdd(&pos_out[rr * 3 + 1], sdy[ew] * fac);
                        atomicAdd(&pos_out[rr * 3 + 2], sdz[ew] * fac);
                    }
                }
        }
    }
}

// ================= node kernel (same mma machinery) =================
__global__ __launch_bounds__(128, 2) void egnn_node_mma(
    const float* __restrict__ h,
    const float* __restrict__ bn1, const float* __restrict__ bn2,
    float* __restrict__ h_out, long long N)
{
    extern __shared__ __align__(16) float smem[];
    char* sb = (char*)smem;
    const uint32_t sbase = smem_u32(smem);
    float* xbf  = (float*)(sb + XB_B);
    float* sbn1 = (float*)(sb + NBN1_B);
    float* sbn2 = (float*)(sb + NBN2_B);

    const int t = threadIdx.x;
    const int w = t >> 5;
    const int lane = t & 31;
    const int g = lane >> 2;
    const int tig = lane & 3;
    const long long n0 = (long long)blockIdx.x * EPB;

    sbn1[t] = bn1[t];
    sbn2[t] = bn2[t];
    __syncthreads();

    float C[2][16][4];
    const uint32_t xb0 = sbase + XB_B;
    const uint32_t wb0 = sbase + WB_B;
    const int mtg0 = 2 * w;

    // ---------- layer A: K=256 ([h ; agg]), 8 chunks ----------
    CLEAR_C();
    stageW_async(wb0, g_wimg + 16 * 4096, t);
    gather_node_async(xb0, h, n0, N, w, lane);
    CP_COMMIT();
    for (int c = 0; c < 8; c++) {
        if (c > 0) __syncthreads();
        if (c < 7) {
            int b = (c + 1) & 1;
            int cn = c + 1;
            const float* base = (cn < 4) ? (h + (cn & 3) * 32) : (g_agg + (cn & 3) * 32);
            stageW_async(wb0 + b * 16384, g_wimg + (16 + cn) * 4096, t);
            gather_node_async(xb0 + b * 16384, base, n0, N, w, lane);
            CP_COMMIT();
            CP_WAIT(1);
        } else CP_WAIT(0);
        __syncthreads();
        int b = c & 1;
        mma_chunk32(C, xb0 + b * 16384, wb0 + b * 16384, mtg0, 0, 4, lane);
    }
    __syncthreads();

    stageW_async(wb0, g_wimg + 24 * 4096, t);
    CP_COMMIT();

    // epilogue A: silu(C + bn1), tf32 -> X2 full layout
#pragma unroll
    for (int mt = 0; mt < 2; mt++)
#pragma unroll
        for (int nt = 0; nt < 16; nt++)
#pragma unroll
            for (int q = 0; q < 4; q++) {
                int n = nt * 8 + 2 * tig + (q & 1);
                int r = g + 8 * (q >> 1);
                int ew = w * 32 + mt * 16 + r;
                float v = tf32r(silu_f(C[mt][nt][q] + sbn1[n]));
                int frag = (ew >> 4) * 16 + nt;
                int ls = (r & 7) * 4 + (n & 3);
                int rg = (r >> 3) + 2 * ((n & 7) >> 2);
                xbf[frag * 128 + ls * 4 + rg] = v;
            }
    __syncthreads();

    // ---------- layer B: K=128, 4 chunks ----------
    CLEAR_C();
    for (int c = 0; c < 4; c++) {
        if (c > 0) __syncthreads();
        if (c < 3) {
            stageW_async(wb0 + ((c + 1) & 1) * 16384, g_wimg + (24 + c + 1) * 4096, t);
            CP_COMMIT();
            CP_WAIT(1);
        } else CP_WAIT(0);
        __syncthreads();
        mma_chunk32(C, xb0, wb0 + (c & 1) * 16384, mtg0, 4 * c, 16, lane);
    }
    __syncthreads();

    // epilogue B: C + bn2 -> X fragment (fp32), then coalesced residual store
#pragma unroll
    for (int mt = 0; mt < 2; mt++)
#pragma unroll
        for (int nt = 0; nt < 16; nt++)
#pragma unroll
            for (int q = 0; q < 4; q++) {
                int n = nt * 8 + 2 * tig + (q & 1);
                int r = g + 8 * (q >> 1);
                int ew = w * 32 + mt * 16 + r;
                float v = C[mt][nt][q] + sbn2[n];
                int frag = (ew >> 4) * 16 + nt;
                int ls = (r & 7) * 4 + (n & 3);
                int rg = (r >> 3) + 2 * ((n & 7) >> 2);
                xbf[frag * 128 + ls * 4 + rg] = v;
            }
    __syncthreads();

    {
        int j = t;
#pragma unroll 4
        for (int el = 0; el < 128; el++) {
            long long n = n0 + el;
            if (n < N) {
                int r = el & 15;
                int frag = (el >> 4) * 16 + (j >> 3);
                int ls = (r & 7) * 4 + (j & 3);
                int rg = (r >> 3) + 2 * ((j & 7) >> 2);
                float v = xbf[frag * 128 + ls * 4 + rg];
                h_out[n * DD + j] = h[n * DD + j] + v;
            }
        }
    }
}

// ---------------- launcher ----------------
extern "C" void kernel_launch(void* const* d_in, const int* in_sizes, int n_in,
                              void* d_out, int out_size)
{
    const float* h   = (const float*)d_in[0];
    const float* pos = (const float*)d_in[1];
    const int*   ei  = (const int*)d_in[2];
    const float* We1 = (const float*)d_in[3];
    const float* be1 = (const float*)d_in[4];
    const float* We2 = (const float*)d_in[5];
    const float* be2 = (const float*)d_in[6];
    const float* Wn1 = (const float*)d_in[7];
    const float* bn1 = (const float*)d_in[8];
    const float* Wn2 = (const float*)d_in[9];
    const float* bn2 = (const float*)d_in[10];
    const float* Wc1 = (const float*)d_in[11];
    const float* bc1 = (const float*)d_in[12];
    const float* Wc2 = (const float*)d_in[13];

    const long long N = in_sizes[0] / DD;
    const long long E = (long long)in_sizes[2] / 2;

    float* h_out   = (float*)d_out;
    float* pos_out = h_out + N * DD;

    cudaFuncSetAttribute(egnn_edge_mma, cudaFuncAttributeMaxDynamicSharedMemorySize, EDGE_SMEM_BYTES);
    cudaFuncSetAttribute(egnn_node_mma, cudaFuncAttributeMaxDynamicSharedMemorySize, NODE_SMEM_BYTES);

    egnn_detect_kernel<<<1, 1>>>(ei);
    egnn_prep_kernel<<<(28 * 4096 + 255) / 256, 256>>>(We1, We2, Wc1, Wn1, Wn2);

    long long nAgg = N * DD;
    long long nPos = N * 3;
    int ib = (int)((nAgg + 255) / 256);
    egnn_init_kernel<<<ib, 256>>>(pos, pos_out, nAgg, nPos);

    int eb = (int)((E + EPB - 1) / EPB);
    egnn_edge_mma<<<eb, 128, EDGE_SMEM_BYTES>>>(
        h, pos, ei, E, We1, be1, be2, bc1, Wc2, pos_out);

    int nb = (int)((N + EPB - 1) / EPB);
    egnn_node_mma<<<nb, 128, NODE_SMEM_BYTES>>>(
        h, bn1, bn2, h_out, N);
}

// round 9
// speedup vs baseline: 1.9562x; 1.9562x over previous
#include <cuda_runtime.h>
#include <cuda_fp16.h>
#include <cstdint>

#define DD 128
#define EPB 256        // edges (or nodes) per block; 256 threads / 8 warps

__device__ float  g_agg[50000 * 128];
__device__ __half g_h16[50000 * 128];
__device__ __half g_agg16[50000 * 128];
__device__ int    g_is64;
// 14 chunk images x 8192 halves (16KB): We1 0-3, We2 4-5, Wc1 6-7, Wn1 8-11, Wn2 12-13
__device__ __half g_wimg16[14 * 8192];

// ---------------- helpers ----------------
__device__ __forceinline__ uint32_t smem_u32(const void* p) {
    uint32_t a;
    asm("{ .reg .u64 t; cvta.to.shared.u64 t, %1; cvt.u32.u64 %0, t; }" : "=r"(a) : "l"(p));
    return a;
}
__device__ __forceinline__ float silu_f(float x) { return __fdividef(x, 1.0f + __expf(-x)); }
__device__ __forceinline__ int slot_of(int L) { return L ^ ((L >> 3) & 3); }

__device__ __forceinline__ uint4 lds128(uint32_t a) {
    uint4 v;
    asm volatile("ld.shared.v4.b32 {%0,%1,%2,%3}, [%4];"
                 : "=r"(v.x), "=r"(v.y), "=r"(v.z), "=r"(v.w) : "r"(a));
    return v;
}
__device__ __forceinline__ void sts128(uint32_t a, uint4 v) {
    asm volatile("st.shared.v4.b32 [%0], {%1,%2,%3,%4};"
                 :: "r"(a), "r"(v.x), "r"(v.y), "r"(v.z), "r"(v.w) : "memory");
}
__device__ __forceinline__ void mma16(float* c, uint4 a, uint32_t b0, uint32_t b1) {
    asm volatile(
        "mma.sync.aligned.m16n8k16.row.col.f32.f16.f16.f32 "
        "{%0,%1,%2,%3}, {%4,%5,%6,%7}, {%8,%9}, {%0,%1,%2,%3};"
        : "+f"(c[0]), "+f"(c[1]), "+f"(c[2]), "+f"(c[3])
        : "r"(a.x), "r"(a.y), "r"(a.z), "r"(a.w), "r"(b0), "r"(b1));
}
__device__ __forceinline__ uint32_t h2u(float lo, float hi) {
    __half2 h = __floats2half2_rn(lo, hi);
    return *reinterpret_cast<uint32_t*>(&h);
}
#define CP_ASYNC_4(dst, src) \
    asm volatile("cp.async.ca.shared.global [%0], [%1], 4;" :: "r"(dst), "l"(src) : "memory")
#define CP_ASYNC_16(dst, src) \
    asm volatile("cp.async.cg.shared.global [%0], [%1], 16;" :: "r"(dst), "l"(src) : "memory")
#define CP_COMMIT() asm volatile("cp.async.commit_group;" ::: "memory")
#define CP_WAIT(n)  asm volatile("cp.async.wait_group %0;" :: "n"(n) : "memory")

// ---------------- smem map (bytes) ----------------
// X region 64KB: layer1 = two 32KB K=64 chunk rings; layers 2/3 = full 256x128 fp16 (kstot=8).
// W ring: 2 x 16KB.
#define XB_B    0
#define WB_B    65536
#define SROW_B  98304
#define SCOL_B  99328
#define SDX_B   100352
#define SDY_B   101376
#define SDZ_B   102400
#define SID_B   103424
#define SDIST_B 104448
#define W257_B  105472
#define SWC2_B  105984
#define SBE1_B  106496
#define SBE2_B  107008
#define SBC1_B  107520
#define EDGE_SMEM_BYTES 108032

#define NBN1_B  98304
#define NBN2_B  98816
#define NODE_SMEM_BYTES 99328

// ---------------- small kernels ----------------
__global__ void egnn_detect_kernel(const int* __restrict__ ei32) {
    int is64 = 1;
#pragma unroll
    for (int i = 1; i < 64; i += 2)
        if (ei32[i] != 0) is64 = 0;
    g_is64 = is64;
}

__global__ void egnn_init_kernel(const float* __restrict__ pos, const float* __restrict__ h,
                                 float* __restrict__ pos_out,
                                 long long nAgg, long long nPos) {
    long long i = (long long)blockIdx.x * blockDim.x + threadIdx.x;
    if (i < nAgg) { g_agg[i] = 0.0f; g_h16[i] = __float2half(h[i]); }
    if (i < nPos) pos_out[i] = pos[i];
}

__global__ void egnn_conv_agg(long long nAgg) {
    long long i = (long long)blockIdx.x * blockDim.x + threadIdx.x;
    if (i < nAgg) g_agg16[i] = __float2half(g_agg[i]);
}

// Build fp16 B-fragment chunk images. Record = (ntp, ks) of 512B; per lane 16B at slot(lane):
// halves [nt0.b0(k 2tig..+1), nt0.b1(k 8+2tig..), nt1.b0, nt1.b1], n = (ntp*2+sel)*8 + g.
__global__ void egnn_prep_w(const float* __restrict__ We1, const float* __restrict__ We2,
                            const float* __restrict__ Wc1, const float* __restrict__ Wn1,
                            const float* __restrict__ Wn2) {
    int i = blockIdx.x * 256 + threadIdx.x;
    if (i >= 14 * 8192) return;
    int ci = i >> 13;
    int r = i & 8191;
    int rec = r >> 8;
    int lane = (r >> 3) & 31;
    int sub = r & 7;
    int ntp = rec >> 2, ks = rec & 3;
    int g = lane >> 2, tig = lane & 3;
    int n = (ntp * 2 + (sub >> 2)) * 8 + g;
    int k = ks * 16 + ((sub >> 1) & 1) * 8 + 2 * tig + (sub & 1);
    const float* W; int k0;
    if (ci < 4)       { W = We1; k0 = ci * 64; }
    else if (ci < 6)  { W = We2; k0 = (ci - 4) * 64; }
    else if (ci < 8)  { W = Wc1; k0 = (ci - 6) * 64; }
    else if (ci < 12) { W = Wn1; k0 = (ci - 8) * 64; }
    else              { W = Wn2; k0 = (ci - 12) * 64; }
    g_wimg16[ci * 8192 + rec * 256 + slot_of(lane) * 8 + sub] =
        __float2half(W[(k0 + k) * DD + n]);
}

// ---------------- mma core ----------------
// One K=64 chunk = 4 k16-steps. Per warp: 2 m-tiles (etile0, etile0+1), 16 n-tiles.
__device__ __forceinline__ void mma_chunk16(float (&C)[2][16][4], uint32_t xb_u, uint32_t wb_u,
                                            int etile0, int ks0, int kstot, uint32_t slot16) {
#pragma unroll
    for (int ks = 0; ks < 4; ks++) {
        uint4 a0 = lds128(xb_u + (uint32_t)(((etile0 * kstot + ks0 + ks) << 9)) + slot16);
        uint4 a1 = lds128(xb_u + (uint32_t)((((etile0 + 1) * kstot + ks0 + ks) << 9)) + slot16);
#pragma unroll
        for (int ntp = 0; ntp < 8; ntp++) {
            uint4 b = lds128(wb_u + (uint32_t)(((ntp * 4 + ks) << 9)) + slot16);
            mma16(C[0][2 * ntp],     a0, b.x, b.y);
            mma16(C[0][2 * ntp + 1], a0, b.z, b.w);
            mma16(C[1][2 * ntp],     a1, b.x, b.y);
            mma16(C[1][2 * ntp + 1], a1, b.z, b.w);
        }
    }
}

// Stage one 16KB W chunk (256 threads, 4 x cp.async.16 each).
__device__ __forceinline__ void stageW(uint32_t wbuf_u, const __half* __restrict__ img, int t) {
#pragma unroll
    for (int i = 0; i < 4; i++)
        CP_ASYNC_16(wbuf_u + (uint32_t)((i * 256 + t) * 16), (const char*)(img + (i * 256 + t) * 8));
}

// Gather one K=64 fp16 chunk into fragment layout (kstot=4). Warp w owns etiles 2w, 2w+1.
__device__ __forceinline__ void gatherX(uint32_t xbuf_u, int c, int w, int lane, uint32_t slot16,
                                        const __half* __restrict__ hb,
                                        const int* srow, const int* scol) {
    const int g = lane >> 2, tig = lane & 3;
    const int cb = (c & 1) * 64;
#pragma unroll
    for (int mtl = 0; mtl < 2; mtl++) {
        int etile = 2 * w + mtl;
        int nlo = (c < 2 ? srow : scol)[etile * 16 + g];
        int nhi = (c < 2 ? srow : scol)[etile * 16 + g + 8];
        const __half* slo = hb + (long long)nlo * DD + cb + 2 * tig;
        const __half* shi = hb + (long long)nhi * DD + cb + 2 * tig;
#pragma unroll
        for (int ks = 0; ks < 4; ks++) {
            uint32_t rec = xbuf_u + (uint32_t)(((etile * 4 + ks) << 9)) + slot16;
            CP_ASYNC_4(rec + 0,  (const char*)(slo + ks * 16));
            CP_ASYNC_4(rec + 4,  (const char*)(shi + ks * 16));
            CP_ASYNC_4(rec + 8,  (const char*)(slo + ks * 16 + 8));
            CP_ASYNC_4(rec + 12, (const char*)(shi + ks * 16 + 8));
        }
    }
}

// Node variant: contiguous rows n0+idx (clamped), base selects h16/agg16 + feat offset.
__device__ __forceinline__ void gatherN(uint32_t xbuf_u, const __half* __restrict__ hb,
                                        long long n0, long long Nn, int w, int lane, uint32_t slot16) {
    const int g = lane >> 2, tig = lane & 3;
#pragma unroll
    for (int mtl = 0; mtl < 2; mtl++) {
        int etile = 2 * w + mtl;
        long long rlo = n0 + etile * 16 + g;     if (rlo >= Nn) rlo = Nn - 1;
        long long rhi = n0 + etile * 16 + g + 8; if (rhi >= Nn) rhi = Nn - 1;
        const __half* slo = hb + rlo * DD + 2 * tig;
        const __half* shi = hb + rhi * DD + 2 * tig;
#pragma unroll
        for (int ks = 0; ks < 4; ks++) {
            uint32_t rec = xbuf_u + (uint32_t)(((etile * 4 + ks) << 9)) + slot16;
            CP_ASYNC_4(rec + 0,  (const char*)(slo + ks * 16));
            CP_ASYNC_4(rec + 4,  (const char*)(shi + ks * 16));
            CP_ASYNC_4(rec + 8,  (const char*)(slo + ks * 16 + 8));
            CP_ASYNC_4(rec + 12, (const char*)(shi + ks * 16 + 8));
        }
    }
}

#define CLEAR_C() \
    _Pragma("unroll") for (int mt = 0; mt < 2; mt++) \
    _Pragma("unroll") for (int nt = 0; nt < 16; nt++) \
    _Pragma("unroll") for (int q = 0; q < 4; q++) C[mt][nt][q] = 0.0f

// ================= edge kernel =================
__global__ __launch_bounds__(256, 1) void egnn_edge_mma(
    const float* __restrict__ pos, const int* __restrict__ ei32, long long E,
    const float* __restrict__ We1, const float* __restrict__ be1,
    const float* __restrict__ be2, const float* __restrict__ bc1,
    const float* __restrict__ Wc2, float* __restrict__ pos_out)
{
    extern __shared__ __align__(16) float smem[];
    char* sb = (char*)smem;
    const uint32_t sbase = smem_u32(smem);
    __half* xh  = (__half*)(sb + XB_B);
    int*   srow  = (int*)(sb + SROW_B);
    int*   scol  = (int*)(sb + SCOL_B);
    float* sdx   = (float*)(sb + SDX_B);
    float* sdy   = (float*)(sb + SDY_B);
    float* sdz   = (float*)(sb + SDZ_B);
    float* sid   = (float*)(sb + SID_B);
    float* sdist = (float*)(sb + SDIST_B);
    float* w257s = (float*)(sb + W257_B);
    float* swc2  = (float*)(sb + SWC2_B);
    float* sbe1  = (float*)(sb + SBE1_B);
    float* sbe2  = (float*)(sb + SBE2_B);
    float* sbc1  = (float*)(sb + SBC1_B);

    const int t = threadIdx.x;
    const int w = t >> 5;
    const int lane = t & 31;
    const int g = lane >> 2;
    const int tig = lane & 3;
    const uint32_t slot16 = (uint32_t)(slot_of(lane) * 16);
    const long long e0 = (long long)blockIdx.x * EPB;

    {   // edge meta (one edge per thread)
        long long e = e0 + t;
        if (e >= E) e = E - 1;
        int r, c;
        if (g_is64) { r = ei32[2 * e]; c = ei32[2 * (E + e)]; }
        else        { r = ei32[e];     c = ei32[E + e]; }
        srow[t] = r; scol[t] = c;
        float dx = pos[r * 3 + 0] - pos[c * 3 + 0];
        float dy = pos[r * 3 + 1] - pos[c * 3 + 1];
        float dz = pos[r * 3 + 2] - pos[c * 3 + 2];
        float d = sqrtf(dx * dx + dy * dy + dz * dz);
        d = fmaxf(d, 1e-6f);
        sdx[t] = dx; sdy[t] = dy; sdz[t] = dz;
        sid[t] = 1.0f / d; sdist[t] = d;
        if (t < DD) {
            w257s[t] = We1[256 * DD + t];   // dist row kept fp32 (rank-1 update)
            swc2[t]  = Wc2[t];
            sbe1[t]  = be1[t];
            sbe2[t]  = be2[t];
            sbc1[t]  = bc1[t];
        }
    }
    __syncthreads();

    float C[2][16][4];
    const uint32_t xb0 = sbase + XB_B;
    const uint32_t wb0 = sbase + WB_B;
    const int et0 = 2 * w;

    // ---------- layer 1: K=256, 4 pipelined K=64 chunks ----------
    CLEAR_C();
    stageW(wb0, g_wimg16 + 0 * 8192, t);
    gatherX(xb0, 0, w, lane, slot16, g_h16, srow, scol);
    CP_COMMIT();
    for (int c = 0; c < 4; c++) {
        if (c > 0) __syncthreads();
        if (c < 3) {
            int b = (c + 1) & 1;
            stageW(wb0 + b * 16384, g_wimg16 + (c + 1) * 8192, t);
            gatherX(xb0 + b * 32768, c + 1, w, lane, slot16, g_h16, srow, scol);
            CP_COMMIT();
            CP_WAIT(1);
        } else CP_WAIT(0);
        __syncthreads();
        int b = c & 1;
        mma_chunk16(C, xb0 + b * 32768, wb0 + b * 16384, et0, 0, 4, slot16);
    }
    __syncthreads();

    stageW(wb0, g_wimg16 + 4 * 8192, t);   // layer-2 chunk 0 during epilogue
    CP_COMMIT();

    // epilogue 1: + dist*w257 + be1, silu -> fp16 X2 (full layout kstot=8), conflict-free STS.128
#pragma unroll
    for (int mt = 0; mt < 2; mt++) {
        int etile = et0 + mt;
        float d0 = sdist[etile * 16 + g];
        float d1 = sdist[etile * 16 + g + 8];
#pragma unroll
        for (int ks2 = 0; ks2 < 8; ks2++) {
            int nt0 = 2 * ks2, nt1 = nt0 + 1;
            int n00 = nt0 * 8 + 2 * tig, n01 = n00 + 1;
            int n10 = nt1 * 8 + 2 * tig, n11 = n10 + 1;
            float w00 = w257s[n00], w01 = w257s[n01], w10 = w257s[n10], w11 = w257s[n11];
            float b00 = sbe1[n00], b01 = sbe1[n01], b10 = sbe1[n10], b11 = sbe1[n11];
            uint4 v;
            v.x = h2u(silu_f(C[mt][nt0][0] + d0 * w00 + b00), silu_f(C[mt][nt0][1] + d0 * w01 + b01));
            v.y = h2u(silu_f(C[mt][nt0][2] + d1 * w00 + b00), silu_f(C[mt][nt0][3] + d1 * w01 + b01));
            v.z = h2u(silu_f(C[mt][nt1][0] + d0 * w10 + b10), silu_f(C[mt][nt1][1] + d0 * w11 + b11));
            v.w = h2u(silu_f(C[mt][nt1][2] + d1 * w10 + b10), silu_f(C[mt][nt1][3] + d1 * w11 + b11));
            sts128(xb0 + (uint32_t)(((etile * 8 + ks2) << 9)) + slot16, v);
        }
    }
    __syncthreads();

    // ---------- layer 2: K=128, 2 chunks on resident X2 ----------
    CLEAR_C();
    stageW(wb0 + 16384, g_wimg16 + 5 * 8192, t);
    CP_COMMIT();
    CP_WAIT(1);
    __syncthreads();
    mma_chunk16(C, xb0, wb0, et0, 0, 8, slot16);
    __syncthreads();
    stageW(wb0, g_wimg16 + 6 * 8192, t);   // layer-3 chunk 0
    CP_COMMIT();
    CP_WAIT(1);
    __syncthreads();
    mma_chunk16(C, xb0, wb0 + 16384, et0, 4, 8, slot16);
    __syncthreads();
    stageW(wb0 + 16384, g_wimg16 + 7 * 8192, t);   // layer-3 chunk 1
    CP_COMMIT();

    // epilogue 2: msg = silu(C + be2) -> fp16 X3 (overwrite X2)
#pragma unroll
    for (int mt = 0; mt < 2; mt++) {
        int etile = et0 + mt;
#pragma unroll
        for (int ks2 = 0; ks2 < 8; ks2++) {
            int nt0 = 2 * ks2, nt1 = nt0 + 1;
            int n00 = nt0 * 8 + 2 * tig, n01 = n00 + 1;
            int n10 = nt1 * 8 + 2 * tig, n11 = n10 + 1;
            float b00 = sbe2[n00], b01 = sbe2[n01], b10 = sbe2[n10], b11 = sbe2[n11];
            uint4 v;
            v.x = h2u(silu_f(C[mt][nt0][0] + b00), silu_f(C[mt][nt0][1] + b01));
            v.y = h2u(silu_f(C[mt][nt0][2] + b00), silu_f(C[mt][nt0][3] + b01));
            v.z = h2u(silu_f(C[mt][nt1][0] + b10), silu_f(C[mt][nt1][1] + b11));
            v.w = h2u(silu_f(C[mt][nt1][2] + b10), silu_f(C[mt][nt1][3] + b11));
            sts128(xb0 + (uint32_t)(((etile * 8 + ks2) << 9)) + slot16, v);
        }
    }
    __syncthreads();

    // ---------- layer 3: K=128, 2 chunks (weights prestaged) ----------
    CLEAR_C();
    CP_WAIT(1);
    __syncthreads();
    mma_chunk16(C, xb0, wb0, et0, 0, 8, slot16);
    CP_WAIT(0);
    __syncthreads();
    mma_chunk16(C, xb0, wb0 + 16384, et0, 4, 8, slot16);

    // agg scatter from X3 (fp16 -> fp32 atomics, coalesced across j)
    {
        int j = t & 127;
        int eh = t >> 7;
        int ks2 = j >> 4, kcol = j & 15;
        int tigp = (kcol & 7) >> 1, jp = kcol & 1;
        int regp = (kcol >> 3) * 2;
#pragma unroll 4
        for (int el = 0; el < 128; el++) {
            int ew = eh * 128 + el;
            if (e0 + ew < E) {
                int r = ew & 15;
                int lanep = (r & 7) * 4 + tigp;
                int idx = ((ew >> 4) * 8 + ks2) * 256 + slot_of(lanep) * 8 + (regp + (r >> 3)) * 2 + jp;
                float m = __half2float(xh[idx]);
                atomicAdd(&g_agg[(long long)srow[ew] * DD + j], m);
            }
        }
    }

    // coord epilogue: clip(sum_n silu(C + bc1)*wc2) -> pos atomics
    {
        float sp[2][2] = {{0.f, 0.f}, {0.f, 0.f}};
#pragma unroll
        for (int mt = 0; mt < 2; mt++)
#pragma unroll
            for (int nt = 0; nt < 16; nt++)
#pragma unroll
                for (int q = 0; q < 4; q++) {
                    int n = nt * 8 + 2 * tig + (q & 1);
                    sp[mt][q >> 1] += silu_f(C[mt][nt][q] + sbc1[n]) * swc2[n];
                }
#pragma unroll
        for (int mt = 0; mt < 2; mt++)
#pragma unroll
            for (int hb = 0; hb < 2; hb++) {
                float s = sp[mt][hb];
                s += __shfl_xor_sync(0xFFFFFFFFu, s, 1);
                s += __shfl_xor_sync(0xFFFFFFFFu, s, 2);
                sp[mt][hb] = s;
            }
        if (tig == 0) {
#pragma unroll
            for (int mt = 0; mt < 2; mt++)
#pragma unroll
                for (int hb = 0; hb < 2; hb++) {
                    int ew = (et0 + mt) * 16 + g + 8 * hb;
                    if (e0 + ew < E) {
                        float s = fminf(fmaxf(sp[mt][hb], -1.0f), 1.0f);
                        float fac = s * sid[ew];
                        long long rr = srow[ew];
                        atomicAdd(&pos_out[rr * 3 + 0], sdx[ew] * fac);
                        atomicAdd(&pos_out[rr * 3 + 1], sdy[ew] * fac);
                        atomicAdd(&pos_out[rr * 3 + 2], sdz[ew] * fac);
                    }
                }
        }
    }
}

// ================= node kernel (same fp16 machinery) =================
__global__ __launch_bounds__(256, 1) void egnn_node_mma(
    const float* __restrict__ h,
    const float* __restrict__ bn1, const float* __restrict__ bn2,
    float* __restrict__ h_out, long long N)
{
    extern __shared__ __align__(16) float smem[];
    char* sb = (char*)smem;
    const uint32_t sbase = smem_u32(smem);
    float* sbn1 = (float*)(sb + NBN1_B);
    float* sbn2 = (float*)(sb + NBN2_B);

    const int t = threadIdx.x;
    const int w = t >> 5;
    const int lane = t & 31;
    const int g = lane >> 2;
    const int tig = lane & 3;
    const uint32_t slot16 = (uint32_t)(slot_of(lane) * 16);
    const long long n0 = (long long)blockIdx.x * EPB;

    if (t < DD) { sbn1[t] = bn1[t]; sbn2[t] = bn2[t]; }
    __syncthreads();

    float C[2][16][4];
    const uint32_t xb0 = sbase + XB_B;
    const uint32_t wb0 = sbase + WB_B;
    const int et0 = 2 * w;

    // layer A: K=256 ([h16 ; agg16]), 4 chunks
    CLEAR_C();
    stageW(wb0, g_wimg16 + 8 * 8192, t);
    gatherN(xb0, g_h16, n0, N, w, lane, slot16);
    CP_COMMIT();
    for (int c = 0; c < 4; c++) {
        if (c > 0) __syncthreads();
        if (c < 3) {
            int b = (c + 1) & 1;
            int cn = c + 1;
            const __half* base = (cn < 2 ? g_h16 : g_agg16) + (cn & 1) * 64;
            stageW(wb0 + b * 16384, g_wimg16 + (8 + cn) * 8192, t);
            gatherN(xb0 + b * 32768, base, n0, N, w, lane, slot16);
            CP_COMMIT();
            CP_WAIT(1);
        } else CP_WAIT(0);
        __syncthreads();
        int b = c & 1;
        mma_chunk16(C, xb0 + b * 32768, wb0 + b * 16384, et0, 0, 4, slot16);
    }
    __syncthreads();

    stageW(wb0, g_wimg16 + 12 * 8192, t);
    CP_COMMIT();

    // epilogue A: silu(C + bn1) -> fp16 X2
#pragma unroll
    for (int mt = 0; mt < 2; mt++) {
        int etile = et0 + mt;
#pragma unroll
        for (int ks2 = 0; ks2 < 8; ks2++) {
            int nt0 = 2 * ks2, nt1 = nt0 + 1;
            int n00 = nt0 * 8 + 2 * tig, n01 = n00 + 1;
            int n10 = nt1 * 8 + 2 * tig, n11 = n10 + 1;
            float b00 = sbn1[n00], b01 = sbn1[n01], b10 = sbn1[n10], b11 = sbn1[n11];
            uint4 v;
            v.x = h2u(silu_f(C[mt][nt0][0] + b00), silu_f(C[mt][nt0][1] + b01));
            v.y = h2u(silu_f(C[mt][nt0][2] + b00), silu_f(C[mt][nt0][3] + b01));
            v.z = h2u(silu_f(C[mt][nt1][0] + b10), silu_f(C[mt][nt1][1] + b11));
            v.w = h2u(silu_f(C[mt][nt1][2] + b10), silu_f(C[mt][nt1][3] + b11));
            sts128(xb0 + (uint32_t)(((etile * 8 + ks2) << 9)) + slot16, v);
        }
    }
    __syncthreads();

    // layer B: K=128, 2 chunks
    CLEAR_C();
    stageW(wb0 + 16384, g_wimg16 + 13 * 8192, t);
    CP_COMMIT();
    CP_WAIT(1);
    __syncthreads();
    mma_chunk16(C, xb0, wb0, et0, 0, 8, slot16);
    CP_WAIT(0);
    __syncthreads();
    mma_chunk16(C, xb0, wb0 + 16384, et0, 4, 8, slot16);

    // epilogue B: h_out = h + C + bn2 (direct float2 gmem, no smem round-trip)
#pragma unroll
    for (int mt = 0; mt < 2; mt++) {
        int etile = et0 + mt;
#pragma unroll
        for (int nt = 0; nt < 16; nt++) {
            int n = nt * 8 + 2 * tig;
            float b0 = sbn2[n], b1 = sbn2[n + 1];
#pragma unroll
            for (int qh = 0; qh < 2; qh++) {
                long long node = n0 + etile * 16 + g + 8 * qh;
                if (node < N) {
                    float2 hv = *reinterpret_cast<const float2*>(h + node * DD + n);
                    float2 o;
                    o.x = hv.x + C[mt][nt][2 * qh + 0] + b0;
                    o.y = hv.y + C[mt][nt][2 * qh + 1] + b1;
                    *reinterpret_cast<float2*>(h_out + node * DD + n) = o;
                }
            }
        }
    }
}

// ---------------- launcher ----------------
extern "C" void kernel_launch(void* const* d_in, const int* in_sizes, int n_in,
                              void* d_out, int out_size)
{
    const float* h   = (const float*)d_in[0];
    const float* pos = (const float*)d_in[1];
    const int*   ei  = (const int*)d_in[2];
    const float* We1 = (const float*)d_in[3];
    const float* be1 = (const float*)d_in[4];
    const float* We2 = (const float*)d_in[5];
    const float* be2 = (const float*)d_in[6];
    const float* Wn1 = (const float*)d_in[7];
    const float* bn1 = (const float*)d_in[8];
    const float* Wn2 = (const float*)d_in[9];
    const float* bn2 = (const float*)d_in[10];
    const float* Wc1 = (const float*)d_in[11];
    const float* bc1 = (const float*)d_in[12];
    const float* Wc2 = (const float*)d_in[13];

    const long long N = in_sizes[0] / DD;
    const long long E = (long long)in_sizes[2] / 2;

    float* h_out   = (float*)d_out;
    float* pos_out = h_out + N * DD;

    cudaFuncSetAttribute(egnn_edge_mma, cudaFuncAttributeMaxDynamicSharedMemorySize, EDGE_SMEM_BYTES);
    cudaFuncSetAttribute(egnn_node_mma, cudaFuncAttributeMaxDynamicSharedMemorySize, NODE_SMEM_BYTES);

    egnn_detect_kernel<<<1, 1>>>(ei);
    egnn_prep_w<<<(14 * 8192 + 255) / 256, 256>>>(We1, We2, Wc1, Wn1, Wn2);

    long long nAgg = N * DD;
    long long nPos = N * 3;
    egnn_init_kernel<<<(int)((nAgg + 255) / 256), 256>>>(pos, h, pos_out, nAgg, nPos);

    int eb = (int)((E + EPB - 1) / EPB);
    egnn_edge_mma<<<eb, 256, EDGE_SMEM_BYTES>>>(
        pos, ei, E, We1, be1, be2, bc1, Wc2, pos_out);

    egnn_conv_agg<<<(int)((nAgg + 255) / 256), 256>>>(nAgg);

    int nb = (int)((N + EPB - 1) / EPB);
    egnn_node_mma<<<nb, 256, NODE_SMEM_BYTES>>>(
        h, bn1, bn2, h_out, N);
}

// round 10
// speedup vs baseline: 2.0130x; 1.0290x over previous
#include <cuda_runtime.h>
#include <cuda_fp16.h>
#include <cstdint>

#define DD 128
#define EPB 256        // edges (or nodes) per block; 512 threads / 16 warps, 1 etile each

__device__ float  g_agg[50000 * 128];
__device__ __half g_h16[50000 * 128];
__device__ __half g_agg16[50000 * 128];
__device__ int    g_is64;
// 14 chunk images x 8192 halves (16KB each): We1 0-3, We2 4-5, Wc1 6-7, Wn1 8-11, Wn2 12-13
__device__ __half g_wimg16[14 * 8192];

// ---------------- helpers ----------------
__device__ __forceinline__ uint32_t smem_u32(const void* p) {
    uint32_t a;
    asm("{ .reg .u64 t; cvta.to.shared.u64 t, %1; cvt.u32.u64 %0, t; }" : "=r"(a) : "l"(p));
    return a;
}
__device__ __forceinline__ float silu_f(float x) { return __fdividef(x, 1.0f + __expf(-x)); }
__device__ __forceinline__ int slot_of(int L) { return L ^ ((L >> 3) & 3); }

__device__ __forceinline__ uint4 lds128(uint32_t a) {
    uint4 v;
    asm volatile("ld.shared.v4.b32 {%0,%1,%2,%3}, [%4];"
                 : "=r"(v.x), "=r"(v.y), "=r"(v.z), "=r"(v.w) : "r"(a));
    return v;
}
__device__ __forceinline__ void sts128(uint32_t a, uint4 v) {
    asm volatile("st.shared.v4.b32 [%0], {%1,%2,%3,%4};"
                 :: "r"(a), "r"(v.x), "r"(v.y), "r"(v.z), "r"(v.w) : "memory");
}
__device__ __forceinline__ void mma16(float* c, uint4 a, uint32_t b0, uint32_t b1) {
    asm volatile(
        "mma.sync.aligned.m16n8k16.row.col.f32.f16.f16.f32 "
        "{%0,%1,%2,%3}, {%4,%5,%6,%7}, {%8,%9}, {%0,%1,%2,%3};"
        : "+f"(c[0]), "+f"(c[1]), "+f"(c[2]), "+f"(c[3])
        : "r"(a.x), "r"(a.y), "r"(a.z), "r"(a.w), "r"(b0), "r"(b1));
}
__device__ __forceinline__ uint32_t h2u(float lo, float hi) {
    __half2 h = __floats2half2_rn(lo, hi);
    return *reinterpret_cast<uint32_t*>(&h);
}
#define CP_ASYNC_4(dst, src) \
    asm volatile("cp.async.ca.shared.global [%0], [%1], 4;" :: "r"(dst), "l"(src) : "memory")
#define CP_ASYNC_16(dst, src) \
    asm volatile("cp.async.cg.shared.global [%0], [%1], 16;" :: "r"(dst), "l"(src) : "memory")
#define CP_COMMIT() asm volatile("cp.async.commit_group;" ::: "memory")
#define CP_WAIT(n)  asm volatile("cp.async.wait_group %0;" :: "n"(n) : "memory")

// ---------------- smem maps (bytes) ----------------
// Edge: XB 64KB (layer1: two 32KB K=64 lane-local chunk rings; layers 2/3: full 256x128 fp16
//       layout kstot=8). WB: ALL 8 weight chunk images prestaged (128KB). Tables after.
#define XB_B    0
#define WB_B    65536
#define SROW_B  196608
#define SCOL_B  197632
#define SDX_B   198656
#define SDY_B   199680
#define SDZ_B   200704
#define SID_B   201728
#define SDIST_B 202752
#define W257_B  203776
#define SWC2_B  204288
#define SBE1_B  204800
#define SBE2_B  205312
#define SBC1_B  205824
#define EDGE_SMEM_BYTES 206336

// Node: XB 64KB, WB 6 images (96KB), biases.
#define NWB_B   65536
#define NBN1_B  163840
#define NBN2_B  164352
#define NODE_SMEM_BYTES 164864

// ---------------- small kernels ----------------
__global__ void egnn_detect_kernel(const int* __restrict__ ei32) {
    int is64 = 1;
#pragma unroll
    for (int i = 1; i < 64; i += 2)
        if (ei32[i] != 0) is64 = 0;
    g_is64 = is64;
}

__global__ void egnn_init_kernel(const float* __restrict__ pos, const float* __restrict__ h,
                                 float* __restrict__ pos_out,
                                 long long nAgg, long long nPos) {
    long long i = (long long)blockIdx.x * blockDim.x + threadIdx.x;
    if (i < nAgg) { g_agg[i] = 0.0f; g_h16[i] = __float2half(h[i]); }
    if (i < nPos) pos_out[i] = pos[i];
}

__global__ void egnn_conv_agg(long long nAgg) {
    long long i = (long long)blockIdx.x * blockDim.x + threadIdx.x;
    if (i < nAgg) g_agg16[i] = __float2half(g_agg[i]);
}

// fp16 B-fragment chunk images (identical encoding to R9 — proven correct).
__global__ void egnn_prep_w(const float* __restrict__ We1, const float* __restrict__ We2,
                            const float* __restrict__ Wc1, const float* __restrict__ Wn1,
                            const float* __restrict__ Wn2) {
    int i = blockIdx.x * 256 + threadIdx.x;
    if (i >= 14 * 8192) return;
    int ci = i >> 13;
    int r = i & 8191;
    int rec = r >> 8;
    int lane = (r >> 3) & 31;
    int sub = r & 7;
    int ntp = rec >> 2, ks = rec & 3;
    int g = lane >> 2, tig = lane & 3;
    int n = (ntp * 2 + (sub >> 2)) * 8 + g;
    int k = ks * 16 + ((sub >> 1) & 1) * 8 + 2 * tig + (sub & 1);
    const float* W; int k0;
    if (ci < 4)       { W = We1; k0 = ci * 64; }
    else if (ci < 6)  { W = We2; k0 = (ci - 4) * 64; }
    else if (ci < 8)  { W = Wc1; k0 = (ci - 6) * 64; }
    else if (ci < 12) { W = Wn1; k0 = (ci - 8) * 64; }
    else              { W = Wn2; k0 = (ci - 12) * 64; }
    g_wimg16[ci * 8192 + rec * 256 + slot_of(lane) * 8 + sub] =
        __float2half(W[(k0 + k) * DD + n]);
}

// ---------------- mma core (1 etile per warp) ----------------
// 4 k16-steps of one K=64 chunk. xrec_u = X record base for (etile, ks0); W image at wimg_u.
__device__ __forceinline__ void mma_c4(float (&C)[16][4], uint32_t xrec_u, uint32_t wimg_u,
                                       uint32_t slot16) {
#pragma unroll
    for (int ks = 0; ks < 4; ks++) {
        uint4 a = lds128(xrec_u + (uint32_t)(ks << 9) + slot16);
#pragma unroll
        for (int ntp = 0; ntp < 8; ntp++) {
            uint4 b = lds128(wimg_u + (uint32_t)(((ntp * 4 + ks) << 9)) + slot16);
            mma16(C[2 * ntp],     a, b.x, b.y);
            mma16(C[2 * ntp + 1], a, b.z, b.w);
        }
    }
}

// Gather one K=64 fp16 chunk for THIS warp's etile (lane-local slots).
__device__ __forceinline__ void gatherX(uint32_t xbuf_u, int c, int w, int g, int tig,
                                        uint32_t slot16, const __half* __restrict__ hb,
                                        const int* srow, const int* scol) {
    int nlo = (c < 2 ? srow : scol)[w * 16 + g];
    int nhi = (c < 2 ? srow : scol)[w * 16 + g + 8];
    const __half* slo = hb + (long long)nlo * DD + (c & 1) * 64 + 2 * tig;
    const __half* shi = hb + (long long)nhi * DD + (c & 1) * 64 + 2 * tig;
#pragma unroll
    for (int ks = 0; ks < 4; ks++) {
        uint32_t rec = xbuf_u + (uint32_t)(((w * 4 + ks) << 9)) + slot16;
        CP_ASYNC_4(rec + 0,  (const char*)(slo + ks * 16));
        CP_ASYNC_4(rec + 4,  (const char*)(shi + ks * 16));
        CP_ASYNC_4(rec + 8,  (const char*)(slo + ks * 16 + 8));
        CP_ASYNC_4(rec + 12, (const char*)(shi + ks * 16 + 8));
    }
}

// Node gather: contiguous rows n0+idx (clamped).
__device__ __forceinline__ void gatherN(uint32_t xbuf_u, const __half* __restrict__ hb,
                                        long long n0, long long Nn, int w, int g, int tig,
                                        uint32_t slot16) {
    long long rlo = n0 + w * 16 + g;     if (rlo >= Nn) rlo = Nn - 1;
    long long rhi = n0 + w * 16 + g + 8; if (rhi >= Nn) rhi = Nn - 1;
    const __half* slo = hb + rlo * DD + 2 * tig;
    const __half* shi = hb + rhi * DD + 2 * tig;
#pragma unroll
    for (int ks = 0; ks < 4; ks++) {
        uint32_t rec = xbuf_u + (uint32_t)(((w * 4 + ks) << 9)) + slot16;
        CP_ASYNC_4(rec + 0,  (const char*)(slo + ks * 16));
        CP_ASYNC_4(rec + 4,  (const char*)(shi + ks * 16));
        CP_ASYNC_4(rec + 8,  (const char*)(slo + ks * 16 + 8));
        CP_ASYNC_4(rec + 12, (const char*)(shi + ks * 16 + 8));
    }
}

#define CLEAR_C() \
    _Pragma("unroll") for (int nt = 0; nt < 16; nt++) \
    _Pragma("unroll") for (int q = 0; q < 4; q++) C[nt][q] = 0.0f

// ================= edge kernel =================
__global__ __launch_bounds__(512, 1) void egnn_edge_mma(
    const float* __restrict__ pos, const int* __restrict__ ei32, long long E,
    const float* __restrict__ We1, const float* __restrict__ be1,
    const float* __restrict__ be2, const float* __restrict__ bc1,
    const float* __restrict__ Wc2, float* __restrict__ pos_out)
{
    extern __shared__ __align__(16) float smem[];
    char* sb = (char*)smem;
    const uint32_t sbase = smem_u32(smem);
    __half* xh   = (__half*)(sb + XB_B);
    int*   srow  = (int*)(sb + SROW_B);
    int*   scol  = (int*)(sb + SCOL_B);
    float* sdx   = (float*)(sb + SDX_B);
    float* sdy   = (float*)(sb + SDY_B);
    float* sdz   = (float*)(sb + SDZ_B);
    float* sid   = (float*)(sb + SID_B);
    float* sdist = (float*)(sb + SDIST_B);
    float* w257s = (float*)(sb + W257_B);
    float* swc2  = (float*)(sb + SWC2_B);
    float* sbe1  = (float*)(sb + SBE1_B);
    float* sbe2  = (float*)(sb + SBE2_B);
    float* sbc1  = (float*)(sb + SBC1_B);

    const int t = threadIdx.x;
    const int w = t >> 5;
    const int lane = t & 31;
    const int g = lane >> 2;
    const int tig = lane & 3;
    const uint32_t slot16 = (uint32_t)(slot_of(lane) * 16);
    const long long e0 = (long long)blockIdx.x * EPB;

    if (t < EPB) {   // edge meta
        long long e = e0 + t;
        if (e >= E) e = E - 1;
        int r, c;
        if (g_is64) { r = ei32[2 * e]; c = ei32[2 * (E + e)]; }
        else        { r = ei32[e];     c = ei32[E + e]; }
        srow[t] = r; scol[t] = c;
        float dx = pos[r * 3 + 0] - pos[c * 3 + 0];
        float dy = pos[r * 3 + 1] - pos[c * 3 + 1];
        float dz = pos[r * 3 + 2] - pos[c * 3 + 2];
        float d = sqrtf(dx * dx + dy * dy + dz * dz);
        d = fmaxf(d, 1e-6f);
        sdx[t] = dx; sdy[t] = dy; sdz[t] = dz;
        sid[t] = 1.0f / d; sdist[t] = d;
        if (t < DD) {
            w257s[t] = We1[256 * DD + t];   // dist row kept fp32 (rank-1 update)
            swc2[t]  = Wc2[t];
            sbe1[t]  = be1[t];
            sbe2[t]  = be2[t];
            sbc1[t]  = bc1[t];
        }
    }
    __syncthreads();

    float C[16][4];
    const uint32_t xb0 = sbase + XB_B;
    const uint32_t wb0 = sbase + WB_B;

    // ---------- prestage ALL 8 weight chunks + layer-1 gathers (pipelined) ----------
    CLEAR_C();
    {   // G0: all W images (128KB) + gather chunk0
#pragma unroll
        for (int i = 0; i < 16; i++)
            CP_ASYNC_16(wb0 + (uint32_t)((i * 512 + t) * 16),
                        (const char*)(g_wimg16 + ((size_t)i * 512 + t) * 8));
        gatherX(xb0, 0, w, g, tig, slot16, g_h16, srow, scol);
        CP_COMMIT();
    }
    gatherX(xb0 + 32768, 1, w, g, tig, slot16, g_h16, srow, scol);
    CP_COMMIT();                                   // G1

    CP_WAIT(1);                                    // G0 done (W + chunk0)
    __syncthreads();                               // W visible to all warps
    mma_c4(C, xb0 + (uint32_t)((w * 4) << 9), wb0 + 0 * 16384, slot16);

    gatherX(xb0, 2, w, g, tig, slot16, g_h16, srow, scol);
    CP_COMMIT();                                   // G2 (buf0: lane-local, already consumed)
    CP_WAIT(1);                                    // G1 done
    mma_c4(C, xb0 + 32768 + (uint32_t)((w * 4) << 9), wb0 + 1 * 16384, slot16);

    gatherX(xb0 + 32768, 3, w, g, tig, slot16, g_h16, srow, scol);
    CP_COMMIT();                                   // G3
    CP_WAIT(1);                                    // G2 done
    mma_c4(C, xb0 + (uint32_t)((w * 4) << 9), wb0 + 2 * 16384, slot16);

    CP_WAIT(0);                                    // G3 done
    mma_c4(C, xb0 + 32768 + (uint32_t)((w * 4) << 9), wb0 + 3 * 16384, slot16);

    __syncthreads();   // cross-warp: epilogue-1 full-layout overwrites other warps' buf regions

    // epilogue 1: + dist*w257 + be1, silu -> fp16 X2 (full layout kstot=8), lane-local STS.128
    {
        float d0 = sdist[w * 16 + g];
        float d1 = sdist[w * 16 + g + 8];
#pragma unroll
        for (int ks2 = 0; ks2 < 8; ks2++) {
            int nt0 = 2 * ks2, nt1 = nt0 + 1;
            int n00 = nt0 * 8 + 2 * tig, n01 = n00 + 1;
            int n10 = nt1 * 8 + 2 * tig, n11 = n10 + 1;
            float w00 = w257s[n00], w01 = w257s[n01], w10 = w257s[n10], w11 = w257s[n11];
            float b00 = sbe1[n00], b01 = sbe1[n01], b10 = sbe1[n10], b11 = sbe1[n11];
            uint4 v;
            v.x = h2u(silu_f(C[nt0][0] + d0 * w00 + b00), silu_f(C[nt0][1] + d0 * w01 + b01));
            v.y = h2u(silu_f(C[nt0][2] + d1 * w00 + b00), silu_f(C[nt0][3] + d1 * w01 + b01));
            v.z = h2u(silu_f(C[nt1][0] + d0 * w10 + b10), silu_f(C[nt1][1] + d0 * w11 + b11));
            v.w = h2u(silu_f(C[nt1][2] + d1 * w10 + b10), silu_f(C[nt1][3] + d1 * w11 + b11));
            sts128(xb0 + (uint32_t)(((w * 8 + ks2) << 9)) + slot16, v);
        }
    }

    // ---------- layer 2: K=128 on resident X2 (warp-local, no barriers) ----------
    CLEAR_C();
    mma_c4(C, xb0 + (uint32_t)((w * 8) << 9),       wb0 + 4 * 16384, slot16);
    mma_c4(C, xb0 + (uint32_t)(((w * 8 + 4)) << 9), wb0 + 5 * 16384, slot16);

    // epilogue 2: msg = silu(C + be2) -> fp16 X3 (overwrite own region)
#pragma unroll
    for (int ks2 = 0; ks2 < 8; ks2++) {
        int nt0 = 2 * ks2, nt1 = nt0 + 1;
        int n00 = nt0 * 8 + 2 * tig, n01 = n00 + 1;
        int n10 = nt1 * 8 + 2 * tig, n11 = n10 + 1;
        float b00 = sbe2[n00], b01 = sbe2[n01], b10 = sbe2[n10], b11 = sbe2[n11];
        uint4 v;
        v.x = h2u(silu_f(C[nt0][0] + b00), silu_f(C[nt0][1] + b01));
        v.y = h2u(silu_f(C[nt0][2] + b00), silu_f(C[nt0][3] + b01));
        v.z = h2u(silu_f(C[nt1][0] + b10), silu_f(C[nt1][1] + b11));
        v.w = h2u(silu_f(C[nt1][2] + b10), silu_f(C[nt1][3] + b11));
        sts128(xb0 + (uint32_t)(((w * 8 + ks2) << 9)) + slot16, v);
    }

    // ---------- layer 3: K=128 (warp-local) ----------
    CLEAR_C();
    mma_c4(C, xb0 + (uint32_t)((w * 8) << 9),       wb0 + 6 * 16384, slot16);
    mma_c4(C, xb0 + (uint32_t)(((w * 8 + 4)) << 9), wb0 + 7 * 16384, slot16);

    __syncthreads();   // all X3 written before cross-warp agg scatter

    // agg scatter from X3 (fp16 -> fp32 atomics, coalesced across j; 512 threads)
    {
        int j = t & 127;
        int eh = t >> 7;                 // 0..3 -> 64 edges each
        int ks2 = j >> 4, kcol = j & 15;
        int tigp = (kcol & 7) >> 1, jp = kcol & 1;
        int regp = (kcol >> 3) * 2;
#pragma unroll 4
        for (int el = 0; el < 64; el++) {
            int ew = eh * 64 + el;
            if (e0 + ew < E) {
                int r = ew & 15;
                int lanep = (r & 7) * 4 + tigp;
                int idx = ((ew >> 4) * 8 + ks2) * 256 + slot_of(lanep) * 8 + (regp + (r >> 3)) * 2 + jp;
                float m = __half2float(xh[idx]);
                atomicAdd(&g_agg[(long long)srow[ew] * DD + j], m);
            }
        }
    }

    // coord epilogue: clip(sum_n silu(C + bc1)*wc2) -> pos atomics (warp-local)
    {
        float sp[2] = {0.f, 0.f};
#pragma unroll
        for (int nt = 0; nt < 16; nt++)
#pragma unroll
            for (int q = 0; q < 4; q++) {
                int n = nt * 8 + 2 * tig + (q & 1);
                sp[q >> 1] += silu_f(C[nt][q] + sbc1[n]) * swc2[n];
            }
#pragma unroll
        for (int hb = 0; hb < 2; hb++) {
            float s = sp[hb];
            s += __shfl_xor_sync(0xFFFFFFFFu, s, 1);
            s += __shfl_xor_sync(0xFFFFFFFFu, s, 2);
            sp[hb] = s;
        }
        if (tig == 0) {
#pragma unroll
            for (int hb = 0; hb < 2; hb++) {
                int ew = w * 16 + g + 8 * hb;
                if (e0 + ew < E) {
                    float s = fminf(fmaxf(sp[hb], -1.0f), 1.0f);
                    float fac = s * sid[ew];
                    long long rr = srow[ew];
                    atomicAdd(&pos_out[rr * 3 + 0], sdx[ew] * fac);
                    atomicAdd(&pos_out[rr * 3 + 1], sdy[ew] * fac);
                    atomicAdd(&pos_out[rr * 3 + 2], sdz[ew] * fac);
                }
            }
        }
    }
}

// ================= node kernel =================
__global__ __launch_bounds__(512, 1) void egnn_node_mma(
    const float* __restrict__ h,
    const float* __restrict__ bn1, const float* __restrict__ bn2,
    float* __restrict__ h_out, long long N)
{
    extern __shared__ __align__(16) float smem[];
    char* sb = (char*)smem;
    const uint32_t sbase = smem_u32(smem);
    float* sbn1 = (float*)(sb + NBN1_B);
    float* sbn2 = (float*)(sb + NBN2_B);

    const int t = threadIdx.x;
    const int w = t >> 5;
    const int lane = t & 31;
    const int g = lane >> 2;
    const int tig = lane & 3;
    const uint32_t slot16 = (uint32_t)(slot_of(lane) * 16);
    const long long n0 = (long long)blockIdx.x * EPB;

    if (t < DD) { sbn1[t] = bn1[t]; sbn2[t] = bn2[t]; }
    __syncthreads();

    float C[16][4];
    const uint32_t xb0 = sbase + XB_B;
    const uint32_t wb0 = sbase + NWB_B;

    // prestage 6 W images (96KB) + pipelined gathers of [h16 ; agg16]
    CLEAR_C();
    {
#pragma unroll
        for (int i = 0; i < 12; i++)
            CP_ASYNC_16(wb0 + (uint32_t)((i * 512 + t) * 16),
                        (const char*)(g_wimg16 + 8 * 8192 + ((size_t)i * 512 + t) * 8));
        gatherN(xb0, g_h16, n0, N, w, g, tig, slot16);
        CP_COMMIT();                               // G0
    }
    gatherN(xb0 + 32768, g_h16 + 64, n0, N, w, g, tig, slot16);
    CP_COMMIT();                                   // G1

    CP_WAIT(1);
    __syncthreads();
    mma_c4(C, xb0 + (uint32_t)((w * 4) << 9), wb0 + 0 * 16384, slot16);

    gatherN(xb0, g_agg16, n0, N, w, g, tig, slot16);
    CP_COMMIT();                                   // G2
    CP_WAIT(1);
    mma_c4(C, xb0 + 32768 + (uint32_t)((w * 4) << 9), wb0 + 1 * 16384, slot16);

    gatherN(xb0 + 32768, g_agg16 + 64, n0, N, w, g, tig, slot16);
    CP_COMMIT();                                   // G3
    CP_WAIT(1);
    mma_c4(C, xb0 + (uint32_t)((w * 4) << 9), wb0 + 2 * 16384, slot16);

    CP_WAIT(0);
    mma_c4(C, xb0 + 32768 + (uint32_t)((w * 4) << 9), wb0 + 3 * 16384, slot16);

    __syncthreads();   // before full-layout overwrite

    // epilogue A: silu(C + bn1) -> fp16 X2
#pragma unroll
    for (int ks2 = 0; ks2 < 8; ks2++) {
        int nt0 = 2 * ks2, nt1 = nt0 + 1;
        int n00 = nt0 * 8 + 2 * tig, n01 = n00 + 1;
        int n10 = nt1 * 8 + 2 * tig, n11 = n10 + 1;
        float b00 = sbn1[n00], b01 = sbn1[n01], b10 = sbn1[n10], b11 = sbn1[n11];
        uint4 v;
        v.x = h2u(silu_f(C[nt0][0] + b00), silu_f(C[nt0][1] + b01));
        v.y = h2u(silu_f(C[nt0][2] + b00), silu_f(C[nt0][3] + b01));
        v.z = h2u(silu_f(C[nt1][0] + b10), silu_f(C[nt1][1] + b11));
        v.w = h2u(silu_f(C[nt1][2] + b10), silu_f(C[nt1][3] + b11));
        sts128(xb0 + (uint32_t)(((w * 8 + ks2) << 9)) + slot16, v);
    }

    // layer B: K=128 (warp-local)
    CLEAR_C();
    mma_c4(C, xb0 + (uint32_t)((w * 8) << 9),      wb0 + 4 * 16384, slot16);
    mma_c4(C, xb0 + (uint32_t)((w * 8 + 4) << 9),  wb0 + 5 * 16384, slot16);

    // epilogue B: h_out = h + C + bn2 (warp-local float2 stores)
#pragma unroll
    for (int nt = 0; nt < 16; nt++) {
        int n = nt * 8 + 2 * tig;
        float b0 = sbn2[n], b1 = sbn2[n + 1];
#pragma unroll
        for (int qh = 0; qh < 2; qh++) {
            long long node = n0 + w * 16 + g + 8 * qh;
            if (node < N) {
                float2 hv = *reinterpret_cast<const float2*>(h + node * DD + n);
                float2 o;
                o.x = hv.x + C[nt][2 * qh + 0] + b0;
                o.y = hv.y + C[nt][2 * qh + 1] + b1;
                *reinterpret_cast<float2*>(h_out + node * DD + n) = o;
            }
        }
    }
}

// ---------------- launcher ----------------
extern "C" void kernel_launch(void* const* d_in, const int* in_sizes, int n_in,
                              void* d_out, int out_size)
{
    const float* h   = (const float*)d_in[0];
    const float* pos = (const float*)d_in[1];
    const int*   ei  = (const int*)d_in[2];
    const float* We1 = (const float*)d_in[3];
    const float* be1 = (const float*)d_in[4];
    const float* We2 = (const float*)d_in[5];
    const float* be2 = (const float*)d_in[6];
    const float* Wn1 = (const float*)d_in[7];
    const float* bn1 = (const float*)d_in[8];
    const float* Wn2 = (const float*)d_in[9];
    const float* bn2 = (const float*)d_in[10];
    const float* Wc1 = (const float*)d_in[11];
    const float* bc1 = (const float*)d_in[12];
    const float* Wc2 = (const float*)d_in[13];

    const long long N = in_sizes[0] / DD;
    const long long E = (long long)in_sizes[2] / 2;

    float* h_out   = (float*)d_out;
    float* pos_out = h_out + N * DD;

    cudaFuncSetAttribute(egnn_edge_mma, cudaFuncAttributeMaxDynamicSharedMemorySize, EDGE_SMEM_BYTES);
    cudaFuncSetAttribute(egnn_node_mma, cudaFuncAttributeMaxDynamicSharedMemorySize, NODE_SMEM_BYTES);

    egnn_detect_kernel<<<1, 1>>>(ei);
    egnn_prep_w<<<(14 * 8192 + 255) / 256, 256>>>(We1, We2, Wc1, Wn1, Wn2);

    long long nAgg = N * DD;
    long long nPos = N * 3;
    egnn_init_kernel<<<(int)((nAgg + 255) / 256), 256>>>(pos, h, pos_out, nAgg, nPos);

    int eb = (int)((E + EPB - 1) / EPB);
    egnn_edge_mma<<<eb, 512, EDGE_SMEM_BYTES>>>(
        pos, ei, E, We1, be1, be2, bc1, Wc2, pos_out);

    egnn_conv_agg<<<(int)((nAgg + 255) / 256), 256>>>(nAgg);

    int nb = (int)((N + EPB - 1) / EPB);
    egnn_node_mma<<<nb, 512, NODE_SMEM_BYTES>>>(
        h, bn1, bn2, h_out, N);
}

// round 11
// speedup vs baseline: 2.4464x; 1.2153x over previous
#include <cuda_runtime.h>
#include <cuda_fp16.h>
#include <cstdint>

#define DD 128
#define EPB 128        // edges (or nodes) per block; 256 threads / 8 warps

__device__ float  g_agg[50000 * 128];
__device__ __half g_h16[50000 * 128];
__device__ __half g_agg16[50000 * 128];
__device__ int    g_is64;
// 14 chunk images x 8192 halves (16KB): We1 0-3, We2 4-5, Wc1 6-7, Wn1 8-11, Wn2 12-13
__device__ __half g_wimg16[14 * 8192];

// ---------------- helpers ----------------
__device__ __forceinline__ uint32_t smem_u32(const void* p) {
    uint32_t a;
    asm("{ .reg .u64 t; cvta.to.shared.u64 t, %1; cvt.u32.u64 %0, t; }" : "=r"(a) : "l"(p));
    return a;
}
__device__ __forceinline__ float silu_f(float x) { return __fdividef(x, 1.0f + __expf(-x)); }
__device__ __forceinline__ int slot_of(int L) { return L ^ ((L >> 3) & 3); }

__device__ __forceinline__ uint4 lds128(uint32_t a) {
    uint4 v;
    asm volatile("ld.shared.v4.b32 {%0,%1,%2,%3}, [%4];"
                 : "=r"(v.x), "=r"(v.y), "=r"(v.z), "=r"(v.w) : "r"(a));
    return v;
}
__device__ __forceinline__ void sts128(uint32_t a, uint4 v) {
    asm volatile("st.shared.v4.b32 [%0], {%1,%2,%3,%4};"
                 :: "r"(a), "r"(v.x), "r"(v.y), "r"(v.z), "r"(v.w) : "memory");
}
__device__ __forceinline__ void mma16(float* c, uint4 a, uint32_t b0, uint32_t b1) {
    asm volatile(
        "mma.sync.aligned.m16n8k16.row.col.f32.f16.f16.f32 "
        "{%0,%1,%2,%3}, {%4,%5,%6,%7}, {%8,%9}, {%0,%1,%2,%3};"
        : "+f"(c[0]), "+f"(c[1]), "+f"(c[2]), "+f"(c[3])
        : "r"(a.x), "r"(a.y), "r"(a.z), "r"(a.w), "r"(b0), "r"(b1));
}
__device__ __forceinline__ uint32_t h2u(float lo, float hi) {
    __half2 h = __floats2half2_rn(lo, hi);
    return *reinterpret_cast<uint32_t*>(&h);
}
#define CP_ASYNC_4(dst, src) \
    asm volatile("cp.async.ca.shared.global [%0], [%1], 4;" :: "r"(dst), "l"(src) : "memory")
#define CP_ASYNC_16(dst, src) \
    asm volatile("cp.async.cg.shared.global [%0], [%1], 16;" :: "r"(dst), "l"(src) : "memory")
#define CP_COMMIT() asm volatile("cp.async.commit_group;" ::: "memory")
#define CP_WAIT(n)  asm volatile("cp.async.wait_group %0;" :: "n"(n) : "memory")

// ---------------- smem maps (bytes) ----------------
// XB 32KB: layer1 = two 16KB K=64 chunk rings; layers 2/3 = full 128x128 fp16 (kstot=8).
// WB = two 16KB weight-chunk ring slots.
#define XB_B    0
#define WB_B    32768
#define SROW_B  65536
#define SCOL_B  66048
#define SDX_B   66560
#define SDY_B   67072
#define SDZ_B   67584
#define SID_B   68096
#define SDIST_B 68608
#define W257_B  69120
#define SWC2_B  69632
#define SBE1_B  70144
#define SBE2_B  70656
#define SBC1_B  71168
#define SCO_B   71680
#define EDGE_SMEM_BYTES 72192

#define NWB_B   32768
#define NBN1_B  65536
#define NBN2_B  66048
#define NODE_SMEM_BYTES 66560

// ---------------- small kernels ----------------
__global__ void egnn_detect_kernel(const int* __restrict__ ei32) {
    int is64 = 1;
#pragma unroll
    for (int i = 1; i < 64; i += 2)
        if (ei32[i] != 0) is64 = 0;
    g_is64 = is64;
}

__global__ void egnn_init_kernel(const float* __restrict__ pos, const float* __restrict__ h,
                                 float* __restrict__ pos_out,
                                 long long nAgg, long long nPos) {
    long long i = (long long)blockIdx.x * blockDim.x + threadIdx.x;
    if (i < nAgg) { g_agg[i] = 0.0f; g_h16[i] = __float2half(h[i]); }
    if (i < nPos) pos_out[i] = pos[i];
}

__global__ void egnn_conv_agg(long long nAgg) {
    long long i = (long long)blockIdx.x * blockDim.x + threadIdx.x;
    if (i < nAgg) g_agg16[i] = __float2half(g_agg[i]);
}

// fp16 B-fragment chunk images (identical encoding to R9/R10 — proven).
__global__ void egnn_prep_w(const float* __restrict__ We1, const float* __restrict__ We2,
                            const float* __restrict__ Wc1, const float* __restrict__ Wn1,
                            const float* __restrict__ Wn2) {
    int i = blockIdx.x * 256 + threadIdx.x;
    if (i >= 14 * 8192) return;
    int ci = i >> 13;
    int r = i & 8191;
    int rec = r >> 8;
    int lane = (r >> 3) & 31;
    int sub = r & 7;
    int ntp = rec >> 2, ks = rec & 3;
    int g = lane >> 2, tig = lane & 3;
    int n = (ntp * 2 + (sub >> 2)) * 8 + g;
    int k = ks * 16 + ((sub >> 1) & 1) * 8 + 2 * tig + (sub & 1);
    const float* W; int k0;
    if (ci < 4)       { W = We1; k0 = ci * 64; }
    else if (ci < 6)  { W = We2; k0 = (ci - 4) * 64; }
    else if (ci < 8)  { W = Wc1; k0 = (ci - 6) * 64; }
    else if (ci < 12) { W = Wn1; k0 = (ci - 8) * 64; }
    else              { W = Wn2; k0 = (ci - 12) * 64; }
    g_wimg16[ci * 8192 + rec * 256 + slot_of(lane) * 8 + sub] =
        __float2half(W[(k0 + k) * DD + n]);
}

// ---------------- mma core: warp tile = 2 etiles x 64 n (nh half) ----------------
// 4 k16-steps: A 2 LDS/step, B 4 LDS/step, 16 mma/step.
__device__ __forceinline__ void mma_c4(float (&C)[2][8][4], uint32_t xa0, uint32_t xa1,
                                       uint32_t wimg_u, int nh, uint32_t slot16) {
    const uint32_t wnh = wimg_u + (uint32_t)((nh * 4 * 4) << 9);
#pragma unroll
    for (int ks = 0; ks < 4; ks++) {
        uint4 a0 = lds128(xa0 + (uint32_t)(ks << 9) + slot16);
        uint4 a1 = lds128(xa1 + (uint32_t)(ks << 9) + slot16);
#pragma unroll
        for (int l = 0; l < 4; l++) {
            uint4 b = lds128(wnh + (uint32_t)(((l * 4 + ks) << 9)) + slot16);
            mma16(C[0][2 * l],     a0, b.x, b.y);
            mma16(C[0][2 * l + 1], a0, b.z, b.w);
            mma16(C[1][2 * l],     a1, b.x, b.y);
            mma16(C[1][2 * l + 1], a1, b.z, b.w);
        }
    }
}

// Stage one 16KB W chunk (256 threads, 4 x cp.async.16 each).
__device__ __forceinline__ void stageW(uint32_t wbuf_u, const __half* __restrict__ img, int t) {
#pragma unroll
    for (int i = 0; i < 4; i++)
        CP_ASYNC_16(wbuf_u + (uint32_t)((i * 256 + t) * 16), (const char*)(img + (i * 256 + t) * 8));
}

// Gather one K=64 fp16 chunk for etile w (warp w), lane-local slots.
__device__ __forceinline__ void gatherX(uint32_t xbuf_u, int c, int w, int g, int tig,
                                        uint32_t slot16, const __half* __restrict__ hb,
                                        const int* srow, const int* scol) {
    int nlo = (c < 2 ? srow : scol)[w * 16 + g];
    int nhi = (c < 2 ? srow : scol)[w * 16 + g + 8];
    const __half* slo = hb + (long long)nlo * DD + (c & 1) * 64 + 2 * tig;
    const __half* shi = hb + (long long)nhi * DD + (c & 1) * 64 + 2 * tig;
#pragma unroll
    for (int ks = 0; ks < 4; ks++) {
        uint32_t rec = xbuf_u + (uint32_t)(((w * 4 + ks) << 9)) + slot16;
        CP_ASYNC_4(rec + 0,  (const char*)(slo + ks * 16));
        CP_ASYNC_4(rec + 4,  (const char*)(shi + ks * 16));
        CP_ASYNC_4(rec + 8,  (const char*)(slo + ks * 16 + 8));
        CP_ASYNC_4(rec + 12, (const char*)(shi + ks * 16 + 8));
    }
}

// Node gather: contiguous rows n0+idx (clamped).
__device__ __forceinline__ void gatherN(uint32_t xbuf_u, const __half* __restrict__ hb,
                                        long long n0, long long Nn, int w, int g, int tig,
                                        uint32_t slot16) {
    long long rlo = n0 + w * 16 + g;     if (rlo >= Nn) rlo = Nn - 1;
    long long rhi = n0 + w * 16 + g + 8; if (rhi >= Nn) rhi = Nn - 1;
    const __half* slo = hb + rlo * DD + 2 * tig;
    const __half* shi = hb + rhi * DD + 2 * tig;
#pragma unroll
    for (int ks = 0; ks < 4; ks++) {
        uint32_t rec = xbuf_u + (uint32_t)(((w * 4 + ks) << 9)) + slot16;
        CP_ASYNC_4(rec + 0,  (const char*)(slo + ks * 16));
        CP_ASYNC_4(rec + 4,  (const char*)(shi + ks * 16));
        CP_ASYNC_4(rec + 8,  (const char*)(slo + ks * 16 + 8));
        CP_ASYNC_4(rec + 12, (const char*)(shi + ks * 16 + 8));
    }
}

#define CLEAR_C() \
    _Pragma("unroll") for (int mt = 0; mt < 2; mt++) \
    _Pragma("unroll") for (int nl = 0; nl < 8; nl++) \
    _Pragma("unroll") for (int q = 0; q < 4; q++) C[mt][nl][q] = 0.0f

// ================= edge kernel =================
__global__ __launch_bounds__(256, 2) void egnn_edge_mma(
    const float* __restrict__ pos, const int* __restrict__ ei32, long long E,
    const float* __restrict__ We1, const float* __restrict__ be1,
    const float* __restrict__ be2, const float* __restrict__ bc1,
    const float* __restrict__ Wc2, float* __restrict__ pos_out)
{
    extern __shared__ __align__(16) float smem[];
    char* sb = (char*)smem;
    const uint32_t sbase = smem_u32(smem);
    __half* xh   = (__half*)(sb + XB_B);
    int*   srow  = (int*)(sb + SROW_B);
    int*   scol  = (int*)(sb + SCOL_B);
    float* sdx   = (float*)(sb + SDX_B);
    float* sdy   = (float*)(sb + SDY_B);
    float* sdz   = (float*)(sb + SDZ_B);
    float* sid   = (float*)(sb + SID_B);
    float* sdist = (float*)(sb + SDIST_B);
    float* w257s = (float*)(sb + W257_B);
    float* swc2  = (float*)(sb + SWC2_B);
    float* sbe1  = (float*)(sb + SBE1_B);
    float* sbe2  = (float*)(sb + SBE2_B);
    float* sbc1  = (float*)(sb + SBC1_B);
    float* scoord = (float*)(sb + SCO_B);

    const int t = threadIdx.x;
    const int w = t >> 5;
    const int lane = t & 31;
    const int g = lane >> 2;
    const int tig = lane & 3;
    const int eg = w & 3;          // edge-group: etiles 2eg, 2eg+1
    const int nh = w >> 2;         // n half: nt 8nh .. 8nh+7
    const int e0t = 2 * eg;
    const uint32_t slot16 = (uint32_t)(slot_of(lane) * 16);
    const long long e0 = (long long)blockIdx.x * EPB;

    if (t < EPB) {   // edge meta + tables
        long long e = e0 + t;
        if (e >= E) e = E - 1;
        int r, c;
        if (g_is64) { r = ei32[2 * e]; c = ei32[2 * (E + e)]; }
        else        { r = ei32[e];     c = ei32[E + e]; }
        srow[t] = r; scol[t] = c;
        float dx = pos[r * 3 + 0] - pos[c * 3 + 0];
        float dy = pos[r * 3 + 1] - pos[c * 3 + 1];
        float dz = pos[r * 3 + 2] - pos[c * 3 + 2];
        float d = sqrtf(dx * dx + dy * dy + dz * dz);
        d = fmaxf(d, 1e-6f);
        sdx[t] = dx; sdy[t] = dy; sdz[t] = dz;
        sid[t] = 1.0f / d; sdist[t] = d;
        scoord[t] = 0.0f;
        w257s[t] = We1[256 * DD + t];   // dist row kept fp32 (rank-1 update)
        swc2[t]  = Wc2[t];
        sbe1[t]  = be1[t];
        sbe2[t]  = be2[t];
        sbc1[t]  = bc1[t];
    }
    __syncthreads();

    float C[2][8][4];
    const uint32_t xb0 = sbase + XB_B;
    const uint32_t wb0 = sbase + WB_B;

    // ---------- layer 1: K=256, 4 pipelined K=64 chunks ----------
    CLEAR_C();
    stageW(wb0, g_wimg16 + 0 * 8192, t);
    gatherX(xb0, 0, w, g, tig, slot16, g_h16, srow, scol);
    CP_COMMIT();                                                   // G0
    stageW(wb0 + 16384, g_wimg16 + 1 * 8192, t);
    gatherX(xb0 + 16384, 1, w, g, tig, slot16, g_h16, srow, scol);
    CP_COMMIT();                                                   // G1

#pragma unroll
    for (int c = 0; c < 4; c++) {
        if (c < 3) CP_WAIT(1); else CP_WAIT(0);
        __syncthreads();                       // chunk c (X + W) visible everywhere
        uint32_t bx = xb0 + (uint32_t)((c & 1) * 16384);
        mma_c4(C, bx + (uint32_t)((e0t * 4) << 9), bx + (uint32_t)(((e0t + 1) * 4) << 9),
               wb0 + (uint32_t)((c & 1) * 16384), nh, slot16);
        __syncthreads();                       // all warps done with ring slot c&1
        if (c < 2) {
            stageW(wb0 + (uint32_t)((c & 1) * 16384), g_wimg16 + (c + 2) * 8192, t);
            gatherX(xb0 + (uint32_t)((c & 1) * 16384), c + 2, w, g, tig, slot16,
                    g_h16, srow, scol);
            CP_COMMIT();
        }
    }

    // stage both layer-2 W chunks during epilogue
    stageW(wb0, g_wimg16 + 4 * 8192, t);
    stageW(wb0 + 16384, g_wimg16 + 5 * 8192, t);
    CP_COMMIT();

    // epilogue 1: + dist*w257 + be1, silu -> fp16 X2 (full layout kstot=8), lane-local STS.128
#pragma unroll
    for (int mt = 0; mt < 2; mt++) {
        int etile = e0t + mt;
        float dlo = sdist[etile * 16 + g];
        float dhi = sdist[etile * 16 + g + 8];
#pragma unroll
        for (int l = 0; l < 4; l++) {
            int nt0 = nh * 8 + 2 * l, nt1 = nt0 + 1, ks2 = nh * 4 + l;
            int n00 = nt0 * 8 + 2 * tig, n01 = n00 + 1;
            int n10 = nt1 * 8 + 2 * tig, n11 = n10 + 1;
            float w00 = w257s[n00], w01 = w257s[n01], w10 = w257s[n10], w11 = w257s[n11];
            float b00 = sbe1[n00], b01 = sbe1[n01], b10 = sbe1[n10], b11 = sbe1[n11];
            uint4 v;
            v.x = h2u(silu_f(C[mt][2*l][0] + dlo * w00 + b00), silu_f(C[mt][2*l][1] + dlo * w01 + b01));
            v.y = h2u(silu_f(C[mt][2*l][2] + dhi * w00 + b00), silu_f(C[mt][2*l][3] + dhi * w01 + b01));
            v.z = h2u(silu_f(C[mt][2*l+1][0] + dlo * w10 + b10), silu_f(C[mt][2*l+1][1] + dlo * w11 + b11));
            v.w = h2u(silu_f(C[mt][2*l+1][2] + dhi * w10 + b10), silu_f(C[mt][2*l+1][3] + dhi * w11 + b11));
            sts128(xb0 + (uint32_t)(((etile * 8 + ks2) << 9)) + slot16, v);
        }
    }
    CP_WAIT(0);
    __syncthreads();                           // X2 + L2 weights visible

    // ---------- layer 2: K=128 on resident X2 ----------
    CLEAR_C();
    mma_c4(C, xb0 + (uint32_t)((e0t * 8) << 9), xb0 + (uint32_t)(((e0t + 1) * 8) << 9),
           wb0, nh, slot16);
    mma_c4(C, xb0 + (uint32_t)((e0t * 8 + 4) << 9), xb0 + (uint32_t)(((e0t + 1) * 8 + 4) << 9),
           wb0 + 16384, nh, slot16);
    __syncthreads();                           // everyone done reading X2 + L2 W

    stageW(wb0, g_wimg16 + 6 * 8192, t);
    stageW(wb0 + 16384, g_wimg16 + 7 * 8192, t);
    CP_COMMIT();

    // epilogue 2: msg = silu(C + be2) -> fp16 X3 (overwrite X2)
#pragma unroll
    for (int mt = 0; mt < 2; mt++) {
        int etile = e0t + mt;
#pragma unroll
        for (int l = 0; l < 4; l++) {
            int nt0 = nh * 8 + 2 * l, nt1 = nt0 + 1, ks2 = nh * 4 + l;
            int n00 = nt0 * 8 + 2 * tig, n01 = n00 + 1;
            int n10 = nt1 * 8 + 2 * tig, n11 = n10 + 1;
            float b00 = sbe2[n00], b01 = sbe2[n01], b10 = sbe2[n10], b11 = sbe2[n11];
            uint4 v;
            v.x = h2u(silu_f(C[mt][2*l][0] + b00), silu_f(C[mt][2*l][1] + b01));
            v.y = h2u(silu_f(C[mt][2*l][2] + b00), silu_f(C[mt][2*l][3] + b01));
            v.z = h2u(silu_f(C[mt][2*l+1][0] + b10), silu_f(C[mt][2*l+1][1] + b11));
            v.w = h2u(silu_f(C[mt][2*l+1][2] + b10), silu_f(C[mt][2*l+1][3] + b11));
            sts128(xb0 + (uint32_t)(((etile * 8 + ks2) << 9)) + slot16, v);
        }
    }
    CP_WAIT(0);
    __syncthreads();                           // X3 + L3 weights visible

    // ---------- layer 3: K=128 ----------
    CLEAR_C();
    mma_c4(C, xb0 + (uint32_t)((e0t * 8) << 9), xb0 + (uint32_t)(((e0t + 1) * 8) << 9),
           wb0, nh, slot16);
    mma_c4(C, xb0 + (uint32_t)((e0t * 8 + 4) << 9), xb0 + (uint32_t)(((e0t + 1) * 8 + 4) << 9),
           wb0 + 16384, nh, slot16);
    __syncthreads();                           // X3 stable for scatter

    // agg scatter from X3 (fp16 -> fp32 atomics, coalesced across j; 256 threads, 64 edges each)
    {
        int j = t & 127;
        int eh = t >> 7;
        int ks2 = j >> 4, kcol = j & 15;
        int tigp = (kcol & 7) >> 1, jp = kcol & 1;
        int regp = (kcol >> 3) * 2;
#pragma unroll 4
        for (int el = 0; el < 64; el++) {
            int ew = eh * 64 + el;
            if (e0 + ew < E) {
                int r = ew & 15;
                int lanep = (r & 7) * 4 + tigp;
                int idx = ((ew >> 4) * 8 + ks2) * 256 + slot_of(lanep) * 8 + (regp + (r >> 3)) * 2 + jp;
                float m = __half2float(xh[idx]);
                atomicAdd(&g_agg[(long long)srow[ew] * DD + j], m);
            }
        }
    }

    // coord partials: warp covers only its 64-n half -> combine via smem atomics
    {
        float sp[2][2] = {{0.f, 0.f}, {0.f, 0.f}};
#pragma unroll
        for (int mt = 0; mt < 2; mt++)
#pragma unroll
            for (int nl = 0; nl < 8; nl++)
#pragma unroll
                for (int q = 0; q < 4; q++) {
                    int n = (nh * 8 + nl) * 8 + 2 * tig + (q & 1);
                    sp[mt][q >> 1] += silu_f(C[mt][nl][q] + sbc1[n]) * swc2[n];
                }
#pragma unroll
        for (int mt = 0; mt < 2; mt++)
#pragma unroll
            for (int hb = 0; hb < 2; hb++) {
                float s = sp[mt][hb];
                s += __shfl_xor_sync(0xFFFFFFFFu, s, 1);
                s += __shfl_xor_sync(0xFFFFFFFFu, s, 2);
                sp[mt][hb] = s;
            }
        if (tig == 0) {
#pragma unroll
            for (int mt = 0; mt < 2; mt++)
#pragma unroll
                for (int hb = 0; hb < 2; hb++)
                    atomicAdd(&scoord[(e0t + mt) * 16 + g + 8 * hb], sp[mt][hb]);
        }
    }
    __syncthreads();

    if (t < EPB && e0 + t < E) {
        float s = fminf(fmaxf(scoord[t], -1.0f), 1.0f);
        float fac = s * sid[t];
        long long rr = srow[t];
        atomicAdd(&pos_out[rr * 3 + 0], sdx[t] * fac);
        atomicAdd(&pos_out[rr * 3 + 1], sdy[t] * fac);
        atomicAdd(&pos_out[rr * 3 + 2], sdz[t] * fac);
    }
}

// ================= node kernel =================
__global__ __launch_bounds__(256, 2) void egnn_node_mma(
    const float* __restrict__ h,
    const float* __restrict__ bn1, const float* __restrict__ bn2,
    float* __restrict__ h_out, long long N)
{
    extern __shared__ __align__(16) float smem[];
    char* sb = (char*)smem;
    const uint32_t sbase = smem_u32(smem);
    float* sbn1 = (float*)(sb + NBN1_B);
    float* sbn2 = (float*)(sb + NBN2_B);

    const int t = threadIdx.x;
    const int w = t >> 5;
    const int lane = t & 31;
    const int g = lane >> 2;
    const int tig = lane & 3;
    const int eg = w & 3;
    const int nh = w >> 2;
    const int e0t = 2 * eg;
    const uint32_t slot16 = (uint32_t)(slot_of(lane) * 16);
    const long long n0 = (long long)blockIdx.x * EPB;

    if (t < DD) { sbn1[t] = bn1[t]; sbn2[t] = bn2[t]; }
    __syncthreads();

    float C[2][8][4];
    const uint32_t xb0 = sbase + XB_B;
    const uint32_t wb0 = sbase + NWB_B;

    // layer A: K=256 ([h16 ; agg16]), 4 pipelined chunks
    CLEAR_C();
    stageW(wb0, g_wimg16 + 8 * 8192, t);
    gatherN(xb0, g_h16, n0, N, w, g, tig, slot16);
    CP_COMMIT();
    stageW(wb0 + 16384, g_wimg16 + 9 * 8192, t);
    gatherN(xb0 + 16384, g_h16 + 64, n0, N, w, g, tig, slot16);
    CP_COMMIT();

#pragma unroll
    for (int c = 0; c < 4; c++) {
        if (c < 3) CP_WAIT(1); else CP_WAIT(0);
        __syncthreads();
        uint32_t bx = xb0 + (uint32_t)((c & 1) * 16384);
        mma_c4(C, bx + (uint32_t)((e0t * 4) << 9), bx + (uint32_t)(((e0t + 1) * 4) << 9),
               wb0 + (uint32_t)((c & 1) * 16384), nh, slot16);
        __syncthreads();
        if (c < 2) {
            const __half* base = g_agg16 + (c & 1) * 64;   // chunks 2,3 = agg halves
            stageW(wb0 + (uint32_t)((c & 1) * 16384), g_wimg16 + (10 + c) * 8192, t);
            gatherN(xb0 + (uint32_t)((c & 1) * 16384), base, n0, N, w, g, tig, slot16);
            CP_COMMIT();
        }
    }

    stageW(wb0, g_wimg16 + 12 * 8192, t);
    stageW(wb0 + 16384, g_wimg16 + 13 * 8192, t);
    CP_COMMIT();

    // epilogue A: silu(C + bn1) -> fp16 X2
#pragma unroll
    for (int mt = 0; mt < 2; mt++) {
        int etile = e0t + mt;
#pragma unroll
        for (int l = 0; l < 4; l++) {
            int nt0 = nh * 8 + 2 * l, nt1 = nt0 + 1, ks2 = nh * 4 + l;
            int n00 = nt0 * 8 + 2 * tig, n01 = n00 + 1;
            int n10 = nt1 * 8 + 2 * tig, n11 = n10 + 1;
            float b00 = sbn1[n00], b01 = sbn1[n01], b10 = sbn1[n10], b11 = sbn1[n11];
            uint4 v;
            v.x = h2u(silu_f(C[mt][2*l][0] + b00), silu_f(C[mt][2*l][1] + b01));
            v.y = h2u(silu_f(C[mt][2*l][2] + b00), silu_f(C[mt][2*l][3] + b01));
            v.z = h2u(silu_f(C[mt][2*l+1][0] + b10), silu_f(C[mt][2*l+1][1] + b11));
            v.w = h2u(silu_f(C[mt][2*l+1][2] + b10), silu_f(C[mt][2*l+1][3] + b11));
            sts128(xb0 + (uint32_t)(((etile * 8 + ks2) << 9)) + slot16, v);
        }
    }
    CP_WAIT(0);
    __syncthreads();

    // layer B: K=128
    CLEAR_C();
    mma_c4(C, xb0 + (uint32_t)((e0t * 8) << 9), xb0 + (uint32_t)(((e0t + 1) * 8) << 9),
           wb0, nh, slot16);
    mma_c4(C, xb0 + (uint32_t)((e0t * 8 + 4) << 9), xb0 + (uint32_t)(((e0t + 1) * 8 + 4) << 9),
           wb0 + 16384, nh, slot16);

    // epilogue B: h_out = h + C + bn2 (direct float2 gmem)
#pragma unroll
    for (int mt = 0; mt < 2; mt++) {
        int etile = e0t + mt;
#pragma unroll
        for (int nl = 0; nl < 8; nl++) {
            int n = (nh * 8 + nl) * 8 + 2 * tig;
            float b0 = sbn2[n], b1 = sbn2[n + 1];
#pragma unroll
            for (int qh = 0; qh < 2; qh++) {
                long long node = n0 + etile * 16 + g + 8 * qh;
                if (node < N) {
                    float2 hv = *reinterpret_cast<const float2*>(h + node * DD + n);
                    float2 o;
                    o.x = hv.x + C[mt][nl][2 * qh + 0] + b0;
                    o.y = hv.y + C[mt][nl][2 * qh + 1] + b1;
                    *reinterpret_cast<float2*>(h_out + node * DD + n) = o;
                }
            }
        }
    }
}

// ---------------- launcher ----------------
extern "C" void kernel_launch(void* const* d_in, const int* in_sizes, int n_in,
                              void* d_out, int out_size)
{
    const float* h   = (const float*)d_in[0];
    const float* pos = (const float*)d_in[1];
    const int*   ei  = (const int*)d_in[2];
    const float* We1 = (const float*)d_in[3];
    const float* be1 = (const float*)d_in[4];
    const float* We2 = (const float*)d_in[5];
    const float* be2 = (const float*)d_in[6];
    const float* Wn1 = (const float*)d_in[7];
    const float* bn1 = (const float*)d_in[8];
    const float* Wn2 = (const float*)d_in[9];
    const float* bn2 = (const float*)d_in[10];
    const float* Wc1 = (const float*)d_in[11];
    const float* bc1 = (const float*)d_in[12];
    const float* Wc2 = (const float*)d_in[13];

    const long long N = in_sizes[0] / DD;
    const long long E = (long long)in_sizes[2] / 2;

    float* h_out   = (float*)d_out;
    float* pos_out = h_out + N * DD;

    cudaFuncSetAttribute(egnn_edge_mma, cudaFuncAttributeMaxDynamicSharedMemorySize, EDGE_SMEM_BYTES);
    cudaFuncSetAttribute(egnn_node_mma, cudaFuncAttributeMaxDynamicSharedMemorySize, NODE_SMEM_BYTES);

    egnn_detect_kernel<<<1, 1>>>(ei);
    egnn_prep_w<<<(14 * 8192 + 255) / 256, 256>>>(We1, We2, Wc1, Wn1, Wn2);

    long long nAgg = N * DD;
    long long nPos = N * 3;
    egnn_init_kernel<<<(int)((nAgg + 255) / 256), 256>>>(pos, h, pos_out, nAgg, nPos);

    int eb = (int)((E + EPB - 1) / EPB);
    egnn_edge_mma<<<eb, 256, EDGE_SMEM_BYTES>>>(
        pos, ei, E, We1, be1, be2, bc1, Wc2, pos_out);

    egnn_conv_agg<<<(int)((nAgg + 255) / 256), 256>>>(nAgg);

    int nb = (int)((N + EPB - 1) / EPB);
    egnn_node_mma<<<nb, 256, NODE_SMEM_BYTES>>>(
        h, bn1, bn2, h_out, N);
}

// round 12
// speedup vs baseline: 2.8790x; 1.1768x over previous
#include <cuda_runtime.h>
#include <cuda_fp16.h>
#include <cstdint>

#define DD 128
#define EPB 128        // edges (or nodes) per block; 256 threads / 8 warps

__device__ float  g_agg[50000 * 128];
__device__ __half g_h16[50000 * 128];
__device__ __half g_agg16[50000 * 128];
__device__ int    g_is64;
// 14 chunk images x 8192 halves (16KB): We1 0-3, We2 4-5, Wc1 6-7, Wn1 8-11, Wn2 12-13
__device__ __half g_wimg16[14 * 8192];

// ---------------- helpers ----------------
__device__ __forceinline__ uint32_t smem_u32(const void* p) {
    uint32_t a;
    asm("{ .reg .u64 t; cvta.to.shared.u64 t, %1; cvt.u32.u64 %0, t; }" : "=r"(a) : "l"(p));
    return a;
}
__device__ __forceinline__ float tanh_a(float x) {
    float y;
    asm("tanh.approx.f32 %0, %1;" : "=f"(y) : "f"(x));
    return y;
}
// silu(x) = 0.5*x*(1 + tanh(x/2)) : 1 MUFU + 2 FMA (vs EX2+RCP = 2 MUFU before)
__device__ __forceinline__ float silu_f(float x) {
    float hx = 0.5f * x;
    return hx + hx * tanh_a(hx);
}
__device__ __forceinline__ int slot_of(int L) { return L ^ ((L >> 3) & 3); }

__device__ __forceinline__ uint4 lds128(uint32_t a) {
    uint4 v;
    asm volatile("ld.shared.v4.b32 {%0,%1,%2,%3}, [%4];"
                 : "=r"(v.x), "=r"(v.y), "=r"(v.z), "=r"(v.w) : "r"(a));
    return v;
}
__device__ __forceinline__ void sts128(uint32_t a, uint4 v) {
    asm volatile("st.shared.v4.b32 [%0], {%1,%2,%3,%4};"
                 :: "r"(a), "r"(v.x), "r"(v.y), "r"(v.z), "r"(v.w) : "memory");
}
__device__ __forceinline__ void mma16(float* c, uint4 a, uint32_t b0, uint32_t b1) {
    asm volatile(
        "mma.sync.aligned.m16n8k16.row.col.f32.f16.f16.f32 "
        "{%0,%1,%2,%3}, {%4,%5,%6,%7}, {%8,%9}, {%0,%1,%2,%3};"
        : "+f"(c[0]), "+f"(c[1]), "+f"(c[2]), "+f"(c[3])
        : "r"(a.x), "r"(a.y), "r"(a.z), "r"(a.w), "r"(b0), "r"(b1));
}
__device__ __forceinline__ uint32_t h2u(float lo, float hi) {
    __half2 h = __floats2half2_rn(lo, hi);
    return *reinterpret_cast<uint32_t*>(&h);
}
#define CP_ASYNC_4(dst, src) \
    asm volatile("cp.async.ca.shared.global [%0], [%1], 4;" :: "r"(dst), "l"(src) : "memory")
#define CP_ASYNC_16(dst, src) \
    asm volatile("cp.async.cg.shared.global [%0], [%1], 16;" :: "r"(dst), "l"(src) : "memory")
#define CP_COMMIT() asm volatile("cp.async.commit_group;" ::: "memory")
#define CP_WAIT(n)  asm volatile("cp.async.wait_group %0;" :: "n"(n) : "memory")

// ---------------- smem maps (bytes) ----------------
#define XB_B    0
#define WB_B    32768
#define SROW_B  65536
#define SCOL_B  66048
#define SDX_B   66560
#define SDY_B   67072
#define SDZ_B   67584
#define SID_B   68096
#define SDIST_B 68608
#define W257_B  69120
#define SWC2_B  69632
#define SBE1_B  70144
#define SBE2_B  70656
#define SBC1_B  71168
#define SCO_B   71680
#define EDGE_SMEM_BYTES 72192

#define NWB_B   32768
#define NBN1_B  65536
#define NBN2_B  66048
#define NODE_SMEM_BYTES 66560

// ---------------- small kernels ----------------
__global__ void egnn_detect_kernel(const int* __restrict__ ei32) {
    int is64 = 1;
#pragma unroll
    for (int i = 1; i < 64; i += 2)
        if (ei32[i] != 0) is64 = 0;
    g_is64 = is64;
}

__global__ void egnn_init_kernel(const float* __restrict__ pos, const float* __restrict__ h,
                                 float* __restrict__ pos_out,
                                 long long nAgg, long long nPos) {
    long long i = (long long)blockIdx.x * blockDim.x + threadIdx.x;
    if (i < nAgg) { g_agg[i] = 0.0f; g_h16[i] = __float2half(h[i]); }
    if (i < nPos) pos_out[i] = pos[i];
}

__global__ void egnn_conv_agg(long long nAgg) {
    long long i = (long long)blockIdx.x * blockDim.x + threadIdx.x;
    if (i < nAgg) g_agg16[i] = __float2half(g_agg[i]);
}

// fp16 B-fragment chunk images (identical encoding to R9-R11 — proven).
__global__ void egnn_prep_w(const float* __restrict__ We1, const float* __restrict__ We2,
                            const float* __restrict__ Wc1, const float* __restrict__ Wn1,
                            const float* __restrict__ Wn2) {
    int i = blockIdx.x * 256 + threadIdx.x;
    if (i >= 14 * 8192) return;
    int ci = i >> 13;
    int r = i & 8191;
    int rec = r >> 8;
    int lane = (r >> 3) & 31;
    int sub = r & 7;
    int ntp = rec >> 2, ks = rec & 3;
    int g = lane >> 2, tig = lane & 3;
    int n = (ntp * 2 + (sub >> 2)) * 8 + g;
    int k = ks * 16 + ((sub >> 1) & 1) * 8 + 2 * tig + (sub & 1);
    const float* W; int k0;
    if (ci < 4)       { W = We1; k0 = ci * 64; }
    else if (ci < 6)  { W = We2; k0 = (ci - 4) * 64; }
    else if (ci < 8)  { W = Wc1; k0 = (ci - 6) * 64; }
    else if (ci < 12) { W = Wn1; k0 = (ci - 8) * 64; }
    else              { W = Wn2; k0 = (ci - 12) * 64; }
    g_wimg16[ci * 8192 + rec * 256 + slot_of(lane) * 8 + sub] =
        __float2half(W[(k0 + k) * DD + n]);
}

// ---------------- mma core: warp tile = 2 etiles x 64 n (nh half) ----------------
__device__ __forceinline__ void mma_c4(float (&C)[2][8][4], uint32_t xa0, uint32_t xa1,
                                       uint32_t wimg_u, int nh, uint32_t slot16) {
    const uint32_t wnh = wimg_u + (uint32_t)((nh * 4 * 4) << 9);
#pragma unroll
    for (int ks = 0; ks < 4; ks++) {
        uint4 a0 = lds128(xa0 + (uint32_t)(ks << 9) + slot16);
        uint4 a1 = lds128(xa1 + (uint32_t)(ks << 9) + slot16);
#pragma unroll
        for (int l = 0; l < 4; l++) {
            uint4 b = lds128(wnh + (uint32_t)(((l * 4 + ks) << 9)) + slot16);
            mma16(C[0][2 * l],     a0, b.x, b.y);
            mma16(C[0][2 * l + 1], a0, b.z, b.w);
            mma16(C[1][2 * l],     a1, b.x, b.y);
            mma16(C[1][2 * l + 1], a1, b.z, b.w);
        }
    }
}

__device__ __forceinline__ void stageW(uint32_t wbuf_u, const __half* __restrict__ img, int t) {
#pragma unroll
    for (int i = 0; i < 4; i++)
        CP_ASYNC_16(wbuf_u + (uint32_t)((i * 256 + t) * 16), (const char*)(img + (i * 256 + t) * 8));
}

__device__ __forceinline__ void gatherX(uint32_t xbuf_u, int c, int w, int g, int tig,
                                        uint32_t slot16, const __half* __restrict__ hb,
                                        const int* srow, const int* scol) {
    int nlo = (c < 2 ? srow : scol)[w * 16 + g];
    int nhi = (c < 2 ? srow : scol)[w * 16 + g + 8];
    const __half* slo = hb + (long long)nlo * DD + (c & 1) * 64 + 2 * tig;
    const __half* shi = hb + (long long)nhi * DD + (c & 1) * 64 + 2 * tig;
#pragma unroll
    for (int ks = 0; ks < 4; ks++) {
        uint32_t rec = xbuf_u + (uint32_t)(((w * 4 + ks) << 9)) + slot16;
        CP_ASYNC_4(rec + 0,  (const char*)(slo + ks * 16));
        CP_ASYNC_4(rec + 4,  (const char*)(shi + ks * 16));
        CP_ASYNC_4(rec + 8,  (const char*)(slo + ks * 16 + 8));
        CP_ASYNC_4(rec + 12, (const char*)(shi + ks * 16 + 8));
    }
}

__device__ __forceinline__ void gatherN(uint32_t xbuf_u, const __half* __restrict__ hb,
                                        long long n0, long long Nn, int w, int g, int tig,
                                        uint32_t slot16) {
    long long rlo = n0 + w * 16 + g;     if (rlo >= Nn) rlo = Nn - 1;
    long long rhi = n0 + w * 16 + g + 8; if (rhi >= Nn) rhi = Nn - 1;
    const __half* slo = hb + rlo * DD + 2 * tig;
    const __half* shi = hb + rhi * DD + 2 * tig;
#pragma unroll
    for (int ks = 0; ks < 4; ks++) {
        uint32_t rec = xbuf_u + (uint32_t)(((w * 4 + ks) << 9)) + slot16;
        CP_ASYNC_4(rec + 0,  (const char*)(slo + ks * 16));
        CP_ASYNC_4(rec + 4,  (const char*)(shi + ks * 16));
        CP_ASYNC_4(rec + 8,  (const char*)(slo + ks * 16 + 8));
        CP_ASYNC_4(rec + 12, (const char*)(shi + ks * 16 + 8));
    }
}

#define CLEAR_C() \
    _Pragma("unroll") for (int mt = 0; mt < 2; mt++) \
    _Pragma("unroll") for (int nl = 0; nl < 8; nl++) \
    _Pragma("unroll") for (int q = 0; q < 4; q++) C[mt][nl][q] = 0.0f

// ================= edge kernel =================
__global__ __launch_bounds__(256, 2) void egnn_edge_mma(
    const float* __restrict__ pos, const int* __restrict__ ei32, long long E,
    const float* __restrict__ We1, const float* __restrict__ be1,
    const float* __restrict__ be2, const float* __restrict__ bc1,
    const float* __restrict__ Wc2, float* __restrict__ pos_out)
{
    extern __shared__ __align__(16) float smem[];
    char* sb = (char*)smem;
    const uint32_t sbase = smem_u32(smem);
    __half* xh   = (__half*)(sb + XB_B);
    int*   srow  = (int*)(sb + SROW_B);
    int*   scol  = (int*)(sb + SCOL_B);
    float* sdx   = (float*)(sb + SDX_B);
    float* sdy   = (float*)(sb + SDY_B);
    float* sdz   = (float*)(sb + SDZ_B);
    float* sid   = (float*)(sb + SID_B);
    float* sdist = (float*)(sb + SDIST_B);
    float* w257s = (float*)(sb + W257_B);
    float* swc2  = (float*)(sb + SWC2_B);
    float* sbe1  = (float*)(sb + SBE1_B);
    float* sbe2  = (float*)(sb + SBE2_B);
    float* sbc1  = (float*)(sb + SBC1_B);
    float* scoord = (float*)(sb + SCO_B);

    const int t = threadIdx.x;
    const int w = t >> 5;
    const int lane = t & 31;
    const int g = lane >> 2;
    const int tig = lane & 3;
    const int eg = w & 3;
    const int nh = w >> 2;
    const int e0t = 2 * eg;
    const uint32_t slot16 = (uint32_t)(slot_of(lane) * 16);
    const long long e0 = (long long)blockIdx.x * EPB;

    if (t < EPB) {   // edge meta + tables
        long long e = e0 + t;
        if (e >= E) e = E - 1;
        int r, c;
        if (g_is64) { r = ei32[2 * e]; c = ei32[2 * (E + e)]; }
        else        { r = ei32[e];     c = ei32[E + e]; }
        srow[t] = r; scol[t] = c;
        float dx = pos[r * 3 + 0] - pos[c * 3 + 0];
        float dy = pos[r * 3 + 1] - pos[c * 3 + 1];
        float dz = pos[r * 3 + 2] - pos[c * 3 + 2];
        float d = sqrtf(dx * dx + dy * dy + dz * dz);
        d = fmaxf(d, 1e-6f);
        sdx[t] = dx; sdy[t] = dy; sdz[t] = dz;
        sid[t] = 1.0f / d; sdist[t] = d;
        scoord[t] = 0.0f;
        w257s[t] = We1[256 * DD + t];
        swc2[t]  = Wc2[t];
        sbe1[t]  = be1[t];
        sbe2[t]  = be2[t];
        sbc1[t]  = bc1[t];
    }
    __syncthreads();

    float C[2][8][4];
    const uint32_t xb0 = sbase + XB_B;
    const uint32_t wb0 = sbase + WB_B;

    // ---------- layer 1: K=256, 4 pipelined K=64 chunks ----------
    CLEAR_C();
    stageW(wb0, g_wimg16 + 0 * 8192, t);
    gatherX(xb0, 0, w, g, tig, slot16, g_h16, srow, scol);
    CP_COMMIT();
    stageW(wb0 + 16384, g_wimg16 + 1 * 8192, t);
    gatherX(xb0 + 16384, 1, w, g, tig, slot16, g_h16, srow, scol);
    CP_COMMIT();

#pragma unroll
    for (int c = 0; c < 4; c++) {
        if (c < 3) CP_WAIT(1); else CP_WAIT(0);
        __syncthreads();
        uint32_t bx = xb0 + (uint32_t)((c & 1) * 16384);
        mma_c4(C, bx + (uint32_t)((e0t * 4) << 9), bx + (uint32_t)(((e0t + 1) * 4) << 9),
               wb0 + (uint32_t)((c & 1) * 16384), nh, slot16);
        __syncthreads();
        if (c < 2) {
            stageW(wb0 + (uint32_t)((c & 1) * 16384), g_wimg16 + (c + 2) * 8192, t);
            gatherX(xb0 + (uint32_t)((c & 1) * 16384), c + 2, w, g, tig, slot16,
                    g_h16, srow, scol);
            CP_COMMIT();
        }
    }

    stageW(wb0, g_wimg16 + 4 * 8192, t);
    stageW(wb0 + 16384, g_wimg16 + 5 * 8192, t);
    CP_COMMIT();

    // epilogue 1: + dist*w257 + be1, silu -> fp16 X2
#pragma unroll
    for (int mt = 0; mt < 2; mt++) {
        int etile = e0t + mt;
        float dlo = sdist[etile * 16 + g];
        float dhi = sdist[etile * 16 + g + 8];
#pragma unroll
        for (int l = 0; l < 4; l++) {
            int nt0 = nh * 8 + 2 * l, nt1 = nt0 + 1, ks2 = nh * 4 + l;
            int n00 = nt0 * 8 + 2 * tig, n01 = n00 + 1;
            int n10 = nt1 * 8 + 2 * tig, n11 = n10 + 1;
            float w00 = w257s[n00], w01 = w257s[n01], w10 = w257s[n10], w11 = w257s[n11];
            float b00 = sbe1[n00], b01 = sbe1[n01], b10 = sbe1[n10], b11 = sbe1[n11];
            uint4 v;
            v.x = h2u(silu_f(C[mt][2*l][0] + dlo * w00 + b00), silu_f(C[mt][2*l][1] + dlo * w01 + b01));
            v.y = h2u(silu_f(C[mt][2*l][2] + dhi * w00 + b00), silu_f(C[mt][2*l][3] + dhi * w01 + b01));
            v.z = h2u(silu_f(C[mt][2*l+1][0] + dlo * w10 + b10), silu_f(C[mt][2*l+1][1] + dlo * w11 + b11));
            v.w = h2u(silu_f(C[mt][2*l+1][2] + dhi * w10 + b10), silu_f(C[mt][2*l+1][3] + dhi * w11 + b11));
            sts128(xb0 + (uint32_t)(((etile * 8 + ks2) << 9)) + slot16, v);
        }
    }
    CP_WAIT(0);
    __syncthreads();

    // ---------- layer 2: K=128 on resident X2 ----------
    CLEAR_C();
    mma_c4(C, xb0 + (uint32_t)((e0t * 8) << 9), xb0 + (uint32_t)(((e0t + 1) * 8) << 9),
           wb0, nh, slot16);
    mma_c4(C, xb0 + (uint32_t)((e0t * 8 + 4) << 9), xb0 + (uint32_t)(((e0t + 1) * 8 + 4) << 9),
           wb0 + 16384, nh, slot16);
    __syncthreads();

    stageW(wb0, g_wimg16 + 6 * 8192, t);
    stageW(wb0 + 16384, g_wimg16 + 7 * 8192, t);
    CP_COMMIT();

    // epilogue 2: msg = silu(C + be2) -> fp16 X3
#pragma unroll
    for (int mt = 0; mt < 2; mt++) {
        int etile = e0t + mt;
#pragma unroll
        for (int l = 0; l < 4; l++) {
            int nt0 = nh * 8 + 2 * l, nt1 = nt0 + 1, ks2 = nh * 4 + l;
            int n00 = nt0 * 8 + 2 * tig, n01 = n00 + 1;
            int n10 = nt1 * 8 + 2 * tig, n11 = n10 + 1;
            float b00 = sbe2[n00], b01 = sbe2[n01], b10 = sbe2[n10], b11 = sbe2[n11];
            uint4 v;
            v.x = h2u(silu_f(C[mt][2*l][0] + b00), silu_f(C[mt][2*l][1] + b01));
            v.y = h2u(silu_f(C[mt][2*l][2] + b00), silu_f(C[mt][2*l][3] + b01));
            v.z = h2u(silu_f(C[mt][2*l+1][0] + b10), silu_f(C[mt][2*l+1][1] + b11));
            v.w = h2u(silu_f(C[mt][2*l+1][2] + b10), silu_f(C[mt][2*l+1][3] + b11));
            sts128(xb0 + (uint32_t)(((etile * 8 + ks2) << 9)) + slot16, v);
        }
    }
    CP_WAIT(0);
    __syncthreads();

    // ---------- layer 3: K=128 ----------
    CLEAR_C();
    mma_c4(C, xb0 + (uint32_t)((e0t * 8) << 9), xb0 + (uint32_t)(((e0t + 1) * 8) << 9),
           wb0, nh, slot16);
    mma_c4(C, xb0 + (uint32_t)((e0t * 8 + 4) << 9), xb0 + (uint32_t)(((e0t + 1) * 8 + 4) << 9),
           wb0 + 16384, nh, slot16);
    __syncthreads();

    // agg scatter from X3: precomputed period-16 offset table, full-block fast path
    {
        int j = t & 127;
        int eh = t >> 7;
        int ks2 = j >> 4, kcol = j & 15;
        int tigp = (kcol & 7) >> 1, jp = kcol & 1;
        int regp = (kcol >> 3) * 2;
        int offs[16];
#pragma unroll
        for (int r = 0; r < 16; r++) {
            int lanep = (r & 7) * 4 + tigp;
            offs[r] = ks2 * 256 + slot_of(lanep) * 8 + (regp + (r >> 3)) * 2 + jp;
        }
        float* aggj = g_agg + j;
        if (e0 + EPB <= E) {
#pragma unroll 2
            for (int eq = 0; eq < 4; eq++) {
                int base16 = (eh * 4 + eq) * 2048;
                int ewb = (eh * 4 + eq) * 16;
#pragma unroll
                for (int r = 0; r < 16; r++) {
                    float m = __half2float(xh[base16 + offs[r]]);
                    atomicAdd(aggj + (long long)srow[ewb + r] * DD, m);
                }
            }
        } else {
#pragma unroll 2
            for (int el = 0; el < 64; el++) {
                int ew = eh * 64 + el;
                if (e0 + ew < E) {
                    float m = __half2float(xh[(ew >> 4) * 2048 + offs[ew & 15]]);
                    atomicAdd(aggj + (long long)srow[ew] * DD, m);
                }
            }
        }
    }

    // coord partials -> smem combine
    {
        float sp[2][2] = {{0.f, 0.f}, {0.f, 0.f}};
#pragma unroll
        for (int mt = 0; mt < 2; mt++)
#pragma unroll
            for (int nl = 0; nl < 8; nl++)
#pragma unroll
                for (int q = 0; q < 4; q++) {
                    int n = (nh * 8 + nl) * 8 + 2 * tig + (q & 1);
                    sp[mt][q >> 1] += silu_f(C[mt][nl][q] + sbc1[n]) * swc2[n];
                }
#pragma unroll
        for (int mt = 0; mt < 2; mt++)
#pragma unroll
            for (int hb = 0; hb < 2; hb++) {
                float s = sp[mt][hb];
                s += __shfl_xor_sync(0xFFFFFFFFu, s, 1);
                s += __shfl_xor_sync(0xFFFFFFFFu, s, 2);
                sp[mt][hb] = s;
            }
        if (tig == 0) {
#pragma unroll
            for (int mt = 0; mt < 2; mt++)
#pragma unroll
                for (int hb = 0; hb < 2; hb++)
                    atomicAdd(&scoord[(e0t + mt) * 16 + g + 8 * hb], sp[mt][hb]);
        }
    }
    __syncthreads();

    if (t < EPB && e0 + t < E) {
        float s = fminf(fmaxf(scoord[t], -1.0f), 1.0f);
        float fac = s * sid[t];
        long long rr = srow[t];
        atomicAdd(&pos_out[rr * 3 + 0], sdx[t] * fac);
        atomicAdd(&pos_out[rr * 3 + 1], sdy[t] * fac);
        atomicAdd(&pos_out[rr * 3 + 2], sdz[t] * fac);
    }
}

// ================= node kernel =================
__global__ __launch_bounds__(256, 2) void egnn_node_mma(
    const float* __restrict__ h,
    const float* __restrict__ bn1, const float* __restrict__ bn2,
    float* __restrict__ h_out, long long N)
{
    extern __shared__ __align__(16) float smem[];
    char* sb = (char*)smem;
    const uint32_t sbase = smem_u32(smem);
    float* sbn1 = (float*)(sb + NBN1_B);
    float* sbn2 = (float*)(sb + NBN2_B);

    const int t = threadIdx.x;
    const int w = t >> 5;
    const int lane = t & 31;
    const int g = lane >> 2;
    const int tig = lane & 3;
    const int eg = w & 3;
    const int nh = w >> 2;
    const int e0t = 2 * eg;
    const uint32_t slot16 = (uint32_t)(slot_of(lane) * 16);
    const long long n0 = (long long)blockIdx.x * EPB;

    if (t < DD) { sbn1[t] = bn1[t]; sbn2[t] = bn2[t]; }
    __syncthreads();

    float C[2][8][4];
    const uint32_t xb0 = sbase + XB_B;
    const uint32_t wb0 = sbase + NWB_B;

    CLEAR_C();
    stageW(wb0, g_wimg16 + 8 * 8192, t);
    gatherN(xb0, g_h16, n0, N, w, g, tig, slot16);
    CP_COMMIT();
    stageW(wb0 + 16384, g_wimg16 + 9 * 8192, t);
    gatherN(xb0 + 16384, g_h16 + 64, n0, N, w, g, tig, slot16);
    CP_COMMIT();

#pragma unroll
    for (int c = 0; c < 4; c++) {
        if (c < 3) CP_WAIT(1); else CP_WAIT(0);
        __syncthreads();
        uint32_t bx = xb0 + (uint32_t)((c & 1) * 16384);
        mma_c4(C, bx + (uint32_t)((e0t * 4) << 9), bx + (uint32_t)(((e0t + 1) * 4) << 9),
               wb0 + (uint32_t)((c & 1) * 16384), nh, slot16);
        __syncthreads();
        if (c < 2) {
            const __half* base = g_agg16 + (c & 1) * 64;
            stageW(wb0 + (uint32_t)((c & 1) * 16384), g_wimg16 + (10 + c) * 8192, t);
            gatherN(xb0 + (uint32_t)((c & 1) * 16384), base, n0, N, w, g, tig, slot16);
            CP_COMMIT();
        }
    }

    stageW(wb0, g_wimg16 + 12 * 8192, t);
    stageW(wb0 + 16384, g_wimg16 + 13 * 8192, t);
    CP_COMMIT();

    // epilogue A: silu(C + bn1) -> fp16 X2
#pragma unroll
    for (int mt = 0; mt < 2; mt++) {
        int etile = e0t + mt;
#pragma unroll
        for (int l = 0; l < 4; l++) {
            int nt0 = nh * 8 + 2 * l, nt1 = nt0 + 1, ks2 = nh * 4 + l;
            int n00 = nt0 * 8 + 2 * tig, n01 = n00 + 1;
            int n10 = nt1 * 8 + 2 * tig, n11 = n10 + 1;
            float b00 = sbn1[n00], b01 = sbn1[n01], b10 = sbn1[n10], b11 = sbn1[n11];
            uint4 v;
            v.x = h2u(silu_f(C[mt][2*l][0] + b00), silu_f(C[mt][2*l][1] + b01));
            v.y = h2u(silu_f(C[mt][2*l][2] + b00), silu_f(C[mt][2*l][3] + b01));
            v.z = h2u(silu_f(C[mt][2*l+1][0] + b10), silu_f(C[mt][2*l+1][1] + b11));
            v.w = h2u(silu_f(C[mt][2*l+1][2] + b10), silu_f(C[mt][2*l+1][3] + b11));
            sts128(xb0 + (uint32_t)(((etile * 8 + ks2) << 9)) + slot16, v);
        }
    }
    CP_WAIT(0);
    __syncthreads();

    CLEAR_C();
    mma_c4(C, xb0 + (uint32_t)((e0t * 8) << 9), xb0 + (uint32_t)(((e0t + 1) * 8) << 9),
           wb0, nh, slot16);
    mma_c4(C, xb0 + (uint32_t)((e0t * 8 + 4) << 9), xb0 + (uint32_t)(((e0t + 1) * 8 + 4) << 9),
           wb0 + 16384, nh, slot16);

    // epilogue B: h_out = h + C + bn2
#pragma unroll
    for (int mt = 0; mt < 2; mt++) {
        int etile = e0t + mt;
#pragma unroll
        for (int nl = 0; nl < 8; nl++) {
            int n = (nh * 8 + nl) * 8 + 2 * tig;
            float b0 = sbn2[n], b1 = sbn2[n + 1];
#pragma unroll
            for (int qh = 0; qh < 2; qh++) {
                long long node = n0 + etile * 16 + g + 8 * qh;
                if (node < N) {
                    float2 hv = *reinterpret_cast<const float2*>(h + node * DD + n);
                    float2 o;
                    o.x = hv.x + C[mt][nl][2 * qh + 0] + b0;
                    o.y = hv.y + C[mt][nl][2 * qh + 1] + b1;
                    *reinterpret_cast<float2*>(h_out + node * DD + n) = o;
                }
            }
        }
    }
}

// ---------------- launcher ----------------
extern "C" void kernel_launch(void* const* d_in, const int* in_sizes, int n_in,
                              void* d_out, int out_size)
{
    const float* h   = (const float*)d_in[0];
    const float* pos = (const float*)d_in[1];
    const int*   ei  = (const int*)d_in[2];
    const float* We1 = (const float*)d_in[3];
    const float* be1 = (const float*)d_in[4];
    const float* We2 = (const float*)d_in[5];
    const float* be2 = (const float*)d_in[6];
    const float* Wn1 = (const float*)d_in[7];
    const float* bn1 = (const float*)d_in[8];
    const float* Wn2 = (const float*)d_in[9];
    const float* bn2 = (const float*)d_in[10];
    const float* Wc1 = (const float*)d_in[11];
    const float* bc1 = (const float*)d_in[12];
    const float* Wc2 = (const float*)d_in[13];

    const long long N = in_sizes[0] / DD;
    const long long E = (long long)in_sizes[2] / 2;

    float* h_out   = (float*)d_out;
    float* pos_out = h_out + N * DD;

    cudaFuncSetAttribute(egnn_edge_mma, cudaFuncAttributeMaxDynamicSharedMemorySize, EDGE_SMEM_BYTES);
    cudaFuncSetAttribute(egnn_node_mma, cudaFuncAttributeMaxDynamicSharedMemorySize, NODE_SMEM_BYTES);

    egnn_detect_kernel<<<1, 1>>>(ei);
    egnn_prep_w<<<(14 * 8192 + 255) / 256, 256>>>(We1, We2, Wc1, Wn1, Wn2);

    long long nAgg = N * DD;
    long long nPos = N * 3;
    egnn_init_kernel<<<(int)((nAgg + 255) / 256), 256>>>(pos, h, pos_out, nAgg, nPos);

    int eb = (int)((E + EPB - 1) / EPB);
    egnn_edge_mma<<<eb, 256, EDGE_SMEM_BYTES>>>(
        pos, ei, E, We1, be1, be2, bc1, Wc2, pos_out);

    egnn_conv_agg<<<(int)((nAgg + 255) / 256), 256>>>(nAgg);

    int nb = (int)((N + EPB - 1) / EPB);
    egnn_node_mma<<<nb, 256, NODE_SMEM_BYTES>>>(
        h, bn1, bn2, h_out, N);
}

// round 13
// speedup vs baseline: 2.8918x; 1.0045x over previous
#include <cuda_runtime.h>
#include <cuda_fp16.h>
#include <cstdint>

#define DD 128
#define EPB 128        // edges (or nodes) per block; 256 threads / 8 warps

__device__ float  g_agg[50000 * 128];
__device__ __half g_h16[50000 * 128];
__device__ __half g_agg16[50000 * 128];
__device__ int    g_is64;
// 14 chunk images x 8192 halves (16KB): We1 0-3, We2 4-5, Wc1 6-7, Wn1 8-11, Wn2 12-13
__device__ __half g_wimg16[14 * 8192];

// ---------------- helpers ----------------
__device__ __forceinline__ uint32_t smem_u32(const void* p) {
    uint32_t a;
    asm("{ .reg .u64 t; cvta.to.shared.u64 t, %1; cvt.u32.u64 %0, t; }" : "=r"(a) : "l"(p));
    return a;
}
__device__ __forceinline__ float tanh_a(float x) {
    float y;
    asm("tanh.approx.f32 %0, %1;" : "=f"(y) : "f"(x));
    return y;
}
__device__ __forceinline__ float silu_f(float x) {
    float hx = 0.5f * x;
    return hx + hx * tanh_a(hx);
}
__device__ __forceinline__ int slot_of(int L) { return L ^ ((L >> 3) & 3); }

__device__ __forceinline__ uint4 lds128(uint32_t a) {
    uint4 v;
    asm volatile("ld.shared.v4.b32 {%0,%1,%2,%3}, [%4];"
                 : "=r"(v.x), "=r"(v.y), "=r"(v.z), "=r"(v.w) : "r"(a));
    return v;
}
__device__ __forceinline__ void sts128(uint32_t a, uint4 v) {
    asm volatile("st.shared.v4.b32 [%0], {%1,%2,%3,%4};"
                 :: "r"(a), "r"(v.x), "r"(v.y), "r"(v.z), "r"(v.w) : "memory");
}
__device__ __forceinline__ void mma16(float* c, uint4 a, uint32_t b0, uint32_t b1) {
    asm volatile(
        "mma.sync.aligned.m16n8k16.row.col.f32.f16.f16.f32 "
        "{%0,%1,%2,%3}, {%4,%5,%6,%7}, {%8,%9}, {%0,%1,%2,%3};"
        : "+f"(c[0]), "+f"(c[1]), "+f"(c[2]), "+f"(c[3])
        : "r"(a.x), "r"(a.y), "r"(a.z), "r"(a.w), "r"(b0), "r"(b1));
}
__device__ __forceinline__ uint32_t h2u(float lo, float hi) {
    __half2 h = __floats2half2_rn(lo, hi);
    return *reinterpret_cast<uint32_t*>(&h);
}
#define CP_ASYNC_4(dst, src) \
    asm volatile("cp.async.ca.shared.global [%0], [%1], 4;" :: "r"(dst), "l"(src) : "memory")
#define CP_ASYNC_16(dst, src) \
    asm volatile("cp.async.cg.shared.global [%0], [%1], 16;" :: "r"(dst), "l"(src) : "memory")
#define CP_COMMIT() asm volatile("cp.async.commit_group;" ::: "memory")
#define CP_WAIT(n)  asm volatile("cp.async.wait_group %0;" :: "n"(n) : "memory")

// ---------------- smem maps (bytes) ----------------
#define XB_B    0
#define WB_B    32768
#define SROW_B  65536
#define SCOL_B  66048
#define SDX_B   66560
#define SDY_B   67072
#define SDZ_B   67584
#define SID_B   68096
#define SDIST_B 68608
#define W257_B  69120
#define SWC2_B  69632
#define SBE1_B  70144
#define SBE2_B  70656
#define SBC1_B  71168
#define SCO_B   71680
#define EDGE_SMEM_BYTES 72192

#define NWB_B   32768
#define NBN1_B  65536
#define NBN2_B  66048
#define NODE_SMEM_BYTES 66560

// ---------------- small kernels ----------------
__global__ void egnn_detect_kernel(const int* __restrict__ ei32) {
    int is64 = 1;
#pragma unroll
    for (int i = 1; i < 64; i += 2)
        if (ei32[i] != 0) is64 = 0;
    g_is64 = is64;
}

__global__ void egnn_init_kernel(const float* __restrict__ pos, const float* __restrict__ h,
                                 float* __restrict__ pos_out,
                                 long long nAgg, long long nPos) {
    long long i = (long long)blockIdx.x * blockDim.x + threadIdx.x;
    if (i < nAgg) { g_agg[i] = 0.0f; g_h16[i] = __float2half(h[i]); }
    if (i < nPos) pos_out[i] = pos[i];
}

__global__ void egnn_conv_agg(long long nAgg) {
    long long i = (long long)blockIdx.x * blockDim.x + threadIdx.x;
    if (i < nAgg) g_agg16[i] = __float2half(g_agg[i]);
}

// fp16 B-fragment chunk images (identical encoding to R9-R12 — proven).
__global__ void egnn_prep_w(const float* __restrict__ We1, const float* __restrict__ We2,
                            const float* __restrict__ Wc1, const float* __restrict__ Wn1,
                            const float* __restrict__ Wn2) {
    int i = blockIdx.x * 256 + threadIdx.x;
    if (i >= 14 * 8192) return;
    int ci = i >> 13;
    int r = i & 8191;
    int rec = r >> 8;
    int lane = (r >> 3) & 31;
    int sub = r & 7;
    int ntp = rec >> 2, ks = rec & 3;
    int g = lane >> 2, tig = lane & 3;
    int n = (ntp * 2 + (sub >> 2)) * 8 + g;
    int k = ks * 16 + ((sub >> 1) & 1) * 8 + 2 * tig + (sub & 1);
    const float* W; int k0;
    if (ci < 4)       { W = We1; k0 = ci * 64; }
    else if (ci < 6)  { W = We2; k0 = (ci - 4) * 64; }
    else if (ci < 8)  { W = Wc1; k0 = (ci - 6) * 64; }
    else if (ci < 12) { W = Wn1; k0 = (ci - 8) * 64; }
    else              { W = Wn2; k0 = (ci - 12) * 64; }
    g_wimg16[ci * 8192 + rec * 256 + slot_of(lane) * 8 + sub] =
        __float2half(W[(k0 + k) * DD + n]);
}

// ---------------- mma core: warp tile = 2 etiles x 64 n, SW-PIPELINED LDS ----------------
// Every LDS is issued ~4 mma ahead of its first consumer (volatile order = SASS order).
__device__ __forceinline__ void mma_c4(float (&C)[2][8][4], uint32_t xa0, uint32_t xa1,
                                       uint32_t wimg_u, int nh, uint32_t slot16) {
    const uint32_t wnh = wimg_u + (uint32_t)((nh * 16) << 9);
    uint4 a0 = lds128(xa0 + slot16);
    uint4 a1 = lds128(xa1 + slot16);
    uint4 b0 = lds128(wnh + slot16);                  // (ntp=0, ks=0)
#pragma unroll
    for (int ks = 0; ks < 4; ks++) {
        uint4 b1 = lds128(wnh + (uint32_t)(((1 * 4 + ks) << 9)) + slot16);
        mma16(C[0][0], a0, b0.x, b0.y);
        mma16(C[0][1], a0, b0.z, b0.w);
        mma16(C[1][0], a1, b0.x, b0.y);
        mma16(C[1][1], a1, b0.z, b0.w);
        uint4 b2 = lds128(wnh + (uint32_t)(((2 * 4 + ks) << 9)) + slot16);
        mma16(C[0][2], a0, b1.x, b1.y);
        mma16(C[0][3], a0, b1.z, b1.w);
        mma16(C[1][2], a1, b1.x, b1.y);
        mma16(C[1][3], a1, b1.z, b1.w);
        uint4 b3 = lds128(wnh + (uint32_t)(((3 * 4 + ks) << 9)) + slot16);
        uint4 a0n = a0, a1n = a1;
        if (ks < 3) {
            a0n = lds128(xa0 + (uint32_t)((ks + 1) << 9) + slot16);
            a1n = lds128(xa1 + (uint32_t)((ks + 1) << 9) + slot16);
        }
        mma16(C[0][4], a0, b2.x, b2.y);
        mma16(C[0][5], a0, b2.z, b2.w);
        mma16(C[1][4], a1, b2.x, b2.y);
        mma16(C[1][5], a1, b2.z, b2.w);
        uint4 b0n = b0;
        if (ks < 3) b0n = lds128(wnh + (uint32_t)(((ks + 1) << 9)) + slot16);
        mma16(C[0][6], a0, b3.x, b3.y);
        mma16(C[0][7], a0, b3.z, b3.w);
        mma16(C[1][6], a1, b3.x, b3.y);
        mma16(C[1][7], a1, b3.z, b3.w);
        a0 = a0n; a1 = a1n; b0 = b0n;
    }
}

__device__ __forceinline__ void stageW(uint32_t wbuf_u, const __half* __restrict__ img, int t) {
#pragma unroll
    for (int i = 0; i < 4; i++)
        CP_ASYNC_16(wbuf_u + (uint32_t)((i * 256 + t) * 16), (const char*)(img + (i * 256 + t) * 8));
}

__device__ __forceinline__ void gatherX(uint32_t xbuf_u, int c, int w, int g, int tig,
                                        uint32_t slot16, const __half* __restrict__ hb,
                                        const int* srow, const int* scol) {
    int nlo = (c < 2 ? srow : scol)[w * 16 + g];
    int nhi = (c < 2 ? srow : scol)[w * 16 + g + 8];
    const __half* slo = hb + (long long)nlo * DD + (c & 1) * 64 + 2 * tig;
    const __half* shi = hb + (long long)nhi * DD + (c & 1) * 64 + 2 * tig;
#pragma unroll
    for (int ks = 0; ks < 4; ks++) {
        uint32_t rec = xbuf_u + (uint32_t)(((w * 4 + ks) << 9)) + slot16;
        CP_ASYNC_4(rec + 0,  (const char*)(slo + ks * 16));
        CP_ASYNC_4(rec + 4,  (const char*)(shi + ks * 16));
        CP_ASYNC_4(rec + 8,  (const char*)(slo + ks * 16 + 8));
        CP_ASYNC_4(rec + 12, (const char*)(shi + ks * 16 + 8));
    }
}

__device__ __forceinline__ void gatherN(uint32_t xbuf_u, const __half* __restrict__ hb,
                                        long long n0, long long Nn, int w, int g, int tig,
                                        uint32_t slot16) {
    long long rlo = n0 + w * 16 + g;     if (rlo >= Nn) rlo = Nn - 1;
    long long rhi = n0 + w * 16 + g + 8; if (rhi >= Nn) rhi = Nn - 1;
    const __half* slo = hb + rlo * DD + 2 * tig;
    const __half* shi = hb + rhi * DD + 2 * tig;
#pragma unroll
    for (int ks = 0; ks < 4; ks++) {
        uint32_t rec = xbuf_u + (uint32_t)(((w * 4 + ks) << 9)) + slot16;
        CP_ASYNC_4(rec + 0,  (const char*)(slo + ks * 16));
        CP_ASYNC_4(rec + 4,  (const char*)(shi + ks * 16));
        CP_ASYNC_4(rec + 8,  (const char*)(slo + ks * 16 + 8));
        CP_ASYNC_4(rec + 12, (const char*)(shi + ks * 16 + 8));
    }
}

#define CLEAR_C() \
    _Pragma("unroll") for (int mt = 0; mt < 2; mt++) \
    _Pragma("unroll") for (int nl = 0; nl < 8; nl++) \
    _Pragma("unroll") for (int q = 0; q < 4; q++) C[mt][nl][q] = 0.0f

// ================= edge kernel =================
__global__ __launch_bounds__(256, 2) void egnn_edge_mma(
    const float* __restrict__ pos, const int* __restrict__ ei32, long long E,
    const float* __restrict__ We1, const float* __restrict__ be1,
    const float* __restrict__ be2, const float* __restrict__ bc1,
    const float* __restrict__ Wc2, float* __restrict__ pos_out)
{
    extern __shared__ __align__(16) float smem[];
    char* sb = (char*)smem;
    const uint32_t sbase = smem_u32(smem);
    __half* xh   = (__half*)(sb + XB_B);
    int*   srow  = (int*)(sb + SROW_B);
    int*   scol  = (int*)(sb + SCOL_B);
    float* sdx   = (float*)(sb + SDX_B);
    float* sdy   = (float*)(sb + SDY_B);
    float* sdz   = (float*)(sb + SDZ_B);
    float* sid   = (float*)(sb + SID_B);
    float* sdist = (float*)(sb + SDIST_B);
    float* w257s = (float*)(sb + W257_B);
    float* swc2  = (float*)(sb + SWC2_B);
    float* sbe1  = (float*)(sb + SBE1_B);
    float* sbe2  = (float*)(sb + SBE2_B);
    float* sbc1  = (float*)(sb + SBC1_B);
    float* scoord = (float*)(sb + SCO_B);

    const int t = threadIdx.x;
    const int w = t >> 5;
    const int lane = t & 31;
    const int g = lane >> 2;
    const int tig = lane & 3;
    const int eg = w & 3;
    const int nh = w >> 2;
    const int e0t = 2 * eg;
    const uint32_t slot16 = (uint32_t)(slot_of(lane) * 16);
    const long long e0 = (long long)blockIdx.x * EPB;

    if (t < EPB) {
        long long e = e0 + t;
        if (e >= E) e = E - 1;
        int r, c;
        if (g_is64) { r = ei32[2 * e]; c = ei32[2 * (E + e)]; }
        else        { r = ei32[e];     c = ei32[E + e]; }
        srow[t] = r; scol[t] = c;
        float dx = pos[r * 3 + 0] - pos[c * 3 + 0];
        float dy = pos[r * 3 + 1] - pos[c * 3 + 1];
        float dz = pos[r * 3 + 2] - pos[c * 3 + 2];
        float d = sqrtf(dx * dx + dy * dy + dz * dz);
        d = fmaxf(d, 1e-6f);
        sdx[t] = dx; sdy[t] = dy; sdz[t] = dz;
        sid[t] = 1.0f / d; sdist[t] = d;
        scoord[t] = 0.0f;
        w257s[t] = We1[256 * DD + t];
        swc2[t]  = Wc2[t];
        sbe1[t]  = be1[t];
        sbe2[t]  = be2[t];
        sbc1[t]  = bc1[t];
    }
    __syncthreads();

    float C[2][8][4];
    const uint32_t xb0 = sbase + XB_B;
    const uint32_t wb0 = sbase + WB_B;

    // ---------- layer 1: K=256, 4 pipelined K=64 chunks ----------
    CLEAR_C();
    stageW(wb0, g_wimg16 + 0 * 8192, t);
    gatherX(xb0, 0, w, g, tig, slot16, g_h16, srow, scol);
    CP_COMMIT();
    stageW(wb0 + 16384, g_wimg16 + 1 * 8192, t);
    gatherX(xb0 + 16384, 1, w, g, tig, slot16, g_h16, srow, scol);
    CP_COMMIT();

#pragma unroll
    for (int c = 0; c < 4; c++) {
        if (c < 3) CP_WAIT(1); else CP_WAIT(0);
        __syncthreads();
        uint32_t bx = xb0 + (uint32_t)((c & 1) * 16384);
        mma_c4(C, bx + (uint32_t)((e0t * 4) << 9), bx + (uint32_t)(((e0t + 1) * 4) << 9),
               wb0 + (uint32_t)((c & 1) * 16384), nh, slot16);
        __syncthreads();
        if (c < 2) {
            stageW(wb0 + (uint32_t)((c & 1) * 16384), g_wimg16 + (c + 2) * 8192, t);
            gatherX(xb0 + (uint32_t)((c & 1) * 16384), c + 2, w, g, tig, slot16,
                    g_h16, srow, scol);
            CP_COMMIT();
        }
    }

    stageW(wb0, g_wimg16 + 4 * 8192, t);
    stageW(wb0 + 16384, g_wimg16 + 5 * 8192, t);
    CP_COMMIT();

    // epilogue 1: + dist*w257 + be1, silu -> fp16 X2
#pragma unroll
    for (int mt = 0; mt < 2; mt++) {
        int etile = e0t + mt;
        float dlo = sdist[etile * 16 + g];
        float dhi = sdist[etile * 16 + g + 8];
#pragma unroll
        for (int l = 0; l < 4; l++) {
            int nt0 = nh * 8 + 2 * l, nt1 = nt0 + 1, ks2 = nh * 4 + l;
            int n00 = nt0 * 8 + 2 * tig, n01 = n00 + 1;
            int n10 = nt1 * 8 + 2 * tig, n11 = n10 + 1;
            float w00 = w257s[n00], w01 = w257s[n01], w10 = w257s[n10], w11 = w257s[n11];
            float b00 = sbe1[n00], b01 = sbe1[n01], b10 = sbe1[n10], b11 = sbe1[n11];
            uint4 v;
            v.x = h2u(silu_f(C[mt][2*l][0] + dlo * w00 + b00), silu_f(C[mt][2*l][1] + dlo * w01 + b01));
            v.y = h2u(silu_f(C[mt][2*l][2] + dhi * w00 + b00), silu_f(C[mt][2*l][3] + dhi * w01 + b01));
            v.z = h2u(silu_f(C[mt][2*l+1][0] + dlo * w10 + b10), silu_f(C[mt][2*l+1][1] + dlo * w11 + b11));
            v.w = h2u(silu_f(C[mt][2*l+1][2] + dhi * w10 + b10), silu_f(C[mt][2*l+1][3] + dhi * w11 + b11));
            sts128(xb0 + (uint32_t)(((etile * 8 + ks2) << 9)) + slot16, v);
        }
    }
    CP_WAIT(0);
    __syncthreads();

    // ---------- layer 2: K=128 on resident X2 ----------
    CLEAR_C();
    mma_c4(C, xb0 + (uint32_t)((e0t * 8) << 9), xb0 + (uint32_t)(((e0t + 1) * 8) << 9),
           wb0, nh, slot16);
    mma_c4(C, xb0 + (uint32_t)((e0t * 8 + 4) << 9), xb0 + (uint32_t)(((e0t + 1) * 8 + 4) << 9),
           wb0 + 16384, nh, slot16);
    __syncthreads();

    stageW(wb0, g_wimg16 + 6 * 8192, t);
    stageW(wb0 + 16384, g_wimg16 + 7 * 8192, t);
    CP_COMMIT();

    // epilogue 2: msg = silu(C + be2) -> fp16 X3
#pragma unroll
    for (int mt = 0; mt < 2; mt++) {
        int etile = e0t + mt;
#pragma unroll
        for (int l = 0; l < 4; l++) {
            int nt0 = nh * 8 + 2 * l, nt1 = nt0 + 1, ks2 = nh * 4 + l;
            int n00 = nt0 * 8 + 2 * tig, n01 = n00 + 1;
            int n10 = nt1 * 8 + 2 * tig, n11 = n10 + 1;
            float b00 = sbe2[n00], b01 = sbe2[n01], b10 = sbe2[n10], b11 = sbe2[n11];
            uint4 v;
            v.x = h2u(silu_f(C[mt][2*l][0] + b00), silu_f(C[mt][2*l][1] + b01));
            v.y = h2u(silu_f(C[mt][2*l][2] + b00), silu_f(C[mt][2*l][3] + b01));
            v.z = h2u(silu_f(C[mt][2*l+1][0] + b10), silu_f(C[mt][2*l+1][1] + b11));
            v.w = h2u(silu_f(C[mt][2*l+1][2] + b10), silu_f(C[mt][2*l+1][3] + b11));
            sts128(xb0 + (uint32_t)(((etile * 8 + ks2) << 9)) + slot16, v);
        }
    }
    CP_WAIT(0);
    __syncthreads();

    // ---------- layer 3: K=128 ----------
    CLEAR_C();
    mma_c4(C, xb0 + (uint32_t)((e0t * 8) << 9), xb0 + (uint32_t)(((e0t + 1) * 8) << 9),
           wb0, nh, slot16);
    mma_c4(C, xb0 + (uint32_t)((e0t * 8 + 4) << 9), xb0 + (uint32_t)(((e0t + 1) * 8 + 4) << 9),
           wb0 + 16384, nh, slot16);
    __syncthreads();

    // agg scatter from X3: precomputed period-16 offset table, full-block fast path
    {
        int j = t & 127;
        int eh = t >> 7;
        int ks2 = j >> 4, kcol = j & 15;
        int tigp = (kcol & 7) >> 1, jp = kcol & 1;
        int regp = (kcol >> 3) * 2;
        int offs[16];
#pragma unroll
        for (int r = 0; r < 16; r++) {
            int lanep = (r & 7) * 4 + tigp;
            offs[r] = ks2 * 256 + slot_of(lanep) * 8 + (regp + (r >> 3)) * 2 + jp;
        }
        float* aggj = g_agg + j;
        if (e0 + EPB <= E) {
#pragma unroll 2
            for (int eq = 0; eq < 4; eq++) {
                int base16 = (eh * 4 + eq) * 2048;
                int ewb = (eh * 4 + eq) * 16;
#pragma unroll
                for (int r = 0; r < 16; r++) {
                    float m = __half2float(xh[base16 + offs[r]]);
                    atomicAdd(aggj + (long long)srow[ewb + r] * DD, m);
                }
            }
        } else {
#pragma unroll 2
            for (int el = 0; el < 64; el++) {
                int ew = eh * 64 + el;
                if (e0 + ew < E) {
                    float m = __half2float(xh[(ew >> 4) * 2048 + offs[ew & 15]]);
                    atomicAdd(aggj + (long long)srow[ew] * DD, m);
                }
            }
        }
    }

    // coord partials -> smem combine
    {
        float sp[2][2] = {{0.f, 0.f}, {0.f, 0.f}};
#pragma unroll
        for (int mt = 0; mt < 2; mt++)
#pragma unroll
            for (int nl = 0; nl < 8; nl++)
#pragma unroll
                for (int q = 0; q < 4; q++) {
                    int n = (nh * 8 + nl) * 8 + 2 * tig + (q & 1);
                    sp[mt][q >> 1] += silu_f(C[mt][nl][q] + sbc1[n]) * swc2[n];
                }
#pragma unroll
        for (int mt = 0; mt < 2; mt++)
#pragma unroll
            for (int hb = 0; hb < 2; hb++) {
                float s = sp[mt][hb];
                s += __shfl_xor_sync(0xFFFFFFFFu, s, 1);
                s += __shfl_xor_sync(0xFFFFFFFFu, s, 2);
                sp[mt][hb] = s;
            }
        if (tig == 0) {
#pragma unroll
            for (int mt = 0; mt < 2; mt++)
#pragma unroll
                for (int hb = 0; hb < 2; hb++)
                    atomicAdd(&scoord[(e0t + mt) * 16 + g + 8 * hb], sp[mt][hb]);
        }
    }
    __syncthreads();

    if (t < EPB && e0 + t < E) {
        float s = fminf(fmaxf(scoord[t], -1.0f), 1.0f);
        float fac = s * sid[t];
        long long rr = srow[t];
        atomicAdd(&pos_out[rr * 3 + 0], sdx[t] * fac);
        atomicAdd(&pos_out[rr * 3 + 1], sdy[t] * fac);
        atomicAdd(&pos_out[rr * 3 + 2], sdz[t] * fac);
    }
}

// ================= node kernel =================
__global__ __launch_bounds__(256, 2) void egnn_node_mma(
    const float* __restrict__ h,
    const float* __restrict__ bn1, const float* __restrict__ bn2,
    float* __restrict__ h_out, long long N)
{
    extern __shared__ __align__(16) float smem[];
    char* sb = (char*)smem;
    const uint32_t sbase = smem_u32(smem);
    float* sbn1 = (float*)(sb + NBN1_B);
    float* sbn2 = (float*)(sb + NBN2_B);

    const int t = threadIdx.x;
    const int w = t >> 5;
    const int lane = t & 31;
    const int g = lane >> 2;
    const int tig = lane & 3;
    const int eg = w & 3;
    const int nh = w >> 2;
    const int e0t = 2 * eg;
    const uint32_t slot16 = (uint32_t)(slot_of(lane) * 16);
    const long long n0 = (long long)blockIdx.x * EPB;

    if (t < DD) { sbn1[t] = bn1[t]; sbn2[t] = bn2[t]; }
    __syncthreads();

    float C[2][8][4];
    const uint32_t xb0 = sbase + XB_B;
    const uint32_t wb0 = sbase + NWB_B;

    CLEAR_C();
    stageW(wb0, g_wimg16 + 8 * 8192, t);
    gatherN(xb0, g_h16, n0, N, w, g, tig, slot16);
    CP_COMMIT();
    stageW(wb0 + 16384, g_wimg16 + 9 * 8192, t);
    gatherN(xb0 + 16384, g_h16 + 64, n0, N, w, g, tig, slot16);
    CP_COMMIT();

#pragma unroll
    for (int c = 0; c < 4; c++) {
        if (c < 3) CP_WAIT(1); else CP_WAIT(0);
        __syncthreads();
        uint32_t bx = xb0 + (uint32_t)((c & 1) * 16384);
        mma_c4(C, bx + (uint32_t)((e0t * 4) << 9), bx + (uint32_t)(((e0t + 1) * 4) << 9),
               wb0 + (uint32_t)((c & 1) * 16384), nh, slot16);
        __syncthreads();
        if (c < 2) {
            const __half* base = g_agg16 + (c & 1) * 64;
            stageW(wb0 + (uint32_t)((c & 1) * 16384), g_wimg16 + (10 + c) * 8192, t);
            gatherN(xb0 + (uint32_t)((c & 1) * 16384), base, n0, N, w, g, tig, slot16);
            CP_COMMIT();
        }
    }

    stageW(wb0, g_wimg16 + 12 * 8192, t);
    stageW(wb0 + 16384, g_wimg16 + 13 * 8192, t);
    CP_COMMIT();

    // epilogue A: silu(C + bn1) -> fp16 X2
#pragma unroll
    for (int mt = 0; mt < 2; mt++) {
        int etile = e0t + mt;
#pragma unroll
        for (int l = 0; l < 4; l++) {
            int nt0 = nh * 8 + 2 * l, nt1 = nt0 + 1, ks2 = nh * 4 + l;
            int n00 = nt0 * 8 + 2 * tig, n01 = n00 + 1;
            int n10 = nt1 * 8 + 2 * tig, n11 = n10 + 1;
            float b00 = sbn1[n00], b01 = sbn1[n01], b10 = sbn1[n10], b11 = sbn1[n11];
            uint4 v;
            v.x = h2u(silu_f(C[mt][2*l][0] + b00), silu_f(C[mt][2*l][1] + b01));
            v.y = h2u(silu_f(C[mt][2*l][2] + b00), silu_f(C[mt][2*l][3] + b01));
            v.z = h2u(silu_f(C[mt][2*l+1][0] + b10), silu_f(C[mt][2*l+1][1] + b11));
            v.w = h2u(silu_f(C[mt][2*l+1][2] + b10), silu_f(C[mt][2*l+1][3] + b11));
            sts128(xb0 + (uint32_t)(((etile * 8 + ks2) << 9)) + slot16, v);
        }
    }
    CP_WAIT(0);
    __syncthreads();

    CLEAR_C();
    mma_c4(C, xb0 + (uint32_t)((e0t * 8) << 9), xb0 + (uint32_t)(((e0t + 1) * 8) << 9),
           wb0, nh, slot16);
    mma_c4(C, xb0 + (uint32_t)((e0t * 8 + 4) << 9), xb0 + (uint32_t)(((e0t + 1) * 8 + 4) << 9),
           wb0 + 16384, nh, slot16);

    // epilogue B: h_out = h + C + bn2
#pragma unroll
    for (int mt = 0; mt < 2; mt++) {
        int etile = e0t + mt;
#pragma unroll
        for (int nl = 0; nl < 8; nl++) {
            int n = (nh * 8 + nl) * 8 + 2 * tig;
            float b0 = sbn2[n], b1 = sbn2[n + 1];
#pragma unroll
            for (int qh = 0; qh < 2; qh++) {
                long long node = n0 + etile * 16 + g + 8 * qh;
                if (node < N) {
                    float2 hv = *reinterpret_cast<const float2*>(h + node * DD + n);
                    float2 o;
                    o.x = hv.x + C[mt][nl][2 * qh + 0] + b0;
                    o.y = hv.y + C[mt][nl][2 * qh + 1] + b1;
                    *reinterpret_cast<float2*>(h_out + node * DD + n) = o;
                }
            }
        }
    }
}

// ---------------- launcher ----------------
extern "C" void kernel_launch(void* const* d_in, const int* in_sizes, int n_in,
                              void* d_out, int out_size)
{
    const float* h   = (const float*)d_in[0];
    const float* pos = (const float*)d_in[1];
    const int*   ei  = (const int*)d_in[2];
    const float* We1 = (const float*)d_in[3];
    const float* be1 = (const float*)d_in[4];
    const float* We2 = (const float*)d_in[5];
    const float* be2 = (const float*)d_in[6];
    const float* Wn1 = (const float*)d_in[7];
    const float* bn1 = (const float*)d_in[8];
    const float* Wn2 = (const float*)d_in[9];
    const float* bn2 = (const float*)d_in[10];
    const float* Wc1 = (const float*)d_in[11];
    const float* bc1 = (const float*)d_in[12];
    const float* Wc2 = (const float*)d_in[13];

    const long long N = in_sizes[0] / DD;
    const long long E = (long long)in_sizes[2] / 2;

    float* h_out   = (float*)d_out;
    float* pos_out = h_out + N * DD;

    cudaFuncSetAttribute(egnn_edge_mma, cudaFuncAttributeMaxDynamicSharedMemorySize, EDGE_SMEM_BYTES);
    cudaFuncSetAttribute(egnn_node_mma, cudaFuncAttributeMaxDynamicSharedMemorySize, NODE_SMEM_BYTES);

    egnn_detect_kernel<<<1, 1>>>(ei);
    egnn_prep_w<<<(14 * 8192 + 255) / 256, 256>>>(We1, We2, Wc1, Wn1, Wn2);

    long long nAgg = N * DD;
    long long nPos = N * 3;
    egnn_init_kernel<<<(int)((nAgg + 255) / 256), 256>>>(pos, h, pos_out, nAgg, nPos);

    int eb = (int)((E + EPB - 1) / EPB);
    egnn_edge_mma<<<eb, 256, EDGE_SMEM_BYTES>>>(
        pos, ei, E, We1, be1, be2, bc1, Wc2, pos_out);

    egnn_conv_agg<<<(int)((nAgg + 255) / 256), 256>>>(nAgg);

    int nb = (int)((N + EPB - 1) / EPB);
    egnn_node_mma<<<nb, 256, NODE_SMEM_BYTES>>>(
        h, bn1, bn2, h_out, N);
}

// round 14
// speedup vs baseline: 3.0064x; 1.0396x over previous
#include <cuda_runtime.h>
#include <cuda_fp16.h>
#include <cstdint>

#define DD 128
#define EPB 128        // edges (or nodes) per block; 128 threads / 4 warps

__device__ float  g_agg[50000 * 128];
__device__ __half g_h16[50000 * 128];
__device__ __half g_agg16[50000 * 128];
__device__ int    g_is64;
// 14 chunk images x 8192 halves (16KB): We1 0-3, We2 4-5, Wc1 6-7, Wn1 8-11, Wn2 12-13
__device__ __half g_wimg16[14 * 8192];

// ---------------- helpers ----------------
__device__ __forceinline__ uint32_t smem_u32(const void* p) {
    uint32_t a;
    asm("{ .reg .u64 t; cvta.to.shared.u64 t, %1; cvt.u32.u64 %0, t; }" : "=r"(a) : "l"(p));
    return a;
}
__device__ __forceinline__ float tanh_a(float x) {
    float y;
    asm("tanh.approx.f32 %0, %1;" : "=f"(y) : "f"(x));
    return y;
}
__device__ __forceinline__ float silu_f(float x) {
    float hx = 0.5f * x;
    return hx + hx * tanh_a(hx);
}
__device__ __forceinline__ int slot_of(int L) { return L ^ ((L >> 3) & 3); }

__device__ __forceinline__ uint4 lds128(uint32_t a) {
    uint4 v;
    asm volatile("ld.shared.v4.b32 {%0,%1,%2,%3}, [%4];"
                 : "=r"(v.x), "=r"(v.y), "=r"(v.z), "=r"(v.w) : "r"(a));
    return v;
}
__device__ __forceinline__ void sts128(uint32_t a, uint4 v) {
    asm volatile("st.shared.v4.b32 [%0], {%1,%2,%3,%4};"
                 :: "r"(a), "r"(v.x), "r"(v.y), "r"(v.z), "r"(v.w) : "memory");
}
__device__ __forceinline__ void mma16(float* c, uint4 a, uint32_t b0, uint32_t b1) {
    asm volatile(
        "mma.sync.aligned.m16n8k16.row.col.f32.f16.f16.f32 "
        "{%0,%1,%2,%3}, {%4,%5,%6,%7}, {%8,%9}, {%0,%1,%2,%3};"
        : "+f"(c[0]), "+f"(c[1]), "+f"(c[2]), "+f"(c[3])
        : "r"(a.x), "r"(a.y), "r"(a.z), "r"(a.w), "r"(b0), "r"(b1));
}
__device__ __forceinline__ uint32_t h2u(float lo, float hi) {
    __half2 h = __floats2half2_rn(lo, hi);
    return *reinterpret_cast<uint32_t*>(&h);
}
#define CP_ASYNC_4(dst, src) \
    asm volatile("cp.async.ca.shared.global [%0], [%1], 4;" :: "r"(dst), "l"(src) : "memory")
#define CP_ASYNC_16(dst, src) \
    asm volatile("cp.async.cg.shared.global [%0], [%1], 16;" :: "r"(dst), "l"(src) : "memory")
#define CP_COMMIT() asm volatile("cp.async.commit_group;" ::: "memory")
#define CP_WAIT(n)  asm volatile("cp.async.wait_group %0;" :: "n"(n) : "memory")

// ---------------- smem maps (bytes) ----------------
// XB 32KB: layer1 = two 16KB K=64 chunk slots; later X3 (msg) full 128x128 fp16.
// WB = two 16KB weight-chunk ring slots.
#define XB_B    0
#define WB_B    32768
#define SROW_B  65536
#define SCOL_B  66048
#define SDX_B   66560
#define SDY_B   67072
#define SDZ_B   67584
#define SID_B   68096
#define SDIST_B 68608
#define W257_B  69120
#define SWC2_B  69632
#define SBE1_B  70144
#define SBE2_B  70656
#define SBC1_B  71168
#define EDGE_SMEM_BYTES 71680

#define NWB_B   32768
#define NBN1_B  65536
#define NBN2_B  66048
#define NODE_SMEM_BYTES 66560

// ---------------- small kernels ----------------
__global__ void egnn_detect_kernel(const int* __restrict__ ei32) {
    int is64 = 1;
#pragma unroll
    for (int i = 1; i < 64; i += 2)
        if (ei32[i] != 0) is64 = 0;
    g_is64 = is64;
}

__global__ void egnn_init_kernel(const float* __restrict__ pos, const float* __restrict__ h,
                                 float* __restrict__ pos_out,
                                 long long nAgg, long long nPos) {
    long long i = (long long)blockIdx.x * blockDim.x + threadIdx.x;
    if (i < nAgg) { g_agg[i] = 0.0f; g_h16[i] = __float2half(h[i]); }
    if (i < nPos) pos_out[i] = pos[i];
}

__global__ void egnn_conv_agg(long long nAgg) {
    long long i = (long long)blockIdx.x * blockDim.x + threadIdx.x;
    if (i < nAgg) g_agg16[i] = __float2half(g_agg[i]);
}

// fp16 B-fragment chunk images (identical encoding to R9-R13 — proven).
__global__ void egnn_prep_w(const float* __restrict__ We1, const float* __restrict__ We2,
                            const float* __restrict__ Wc1, const float* __restrict__ Wn1,
                            const float* __restrict__ Wn2) {
    int i = blockIdx.x * 256 + threadIdx.x;
    if (i >= 14 * 8192) return;
    int ci = i >> 13;
    int r = i & 8191;
    int rec = r >> 8;
    int lane = (r >> 3) & 31;
    int sub = r & 7;
    int ntp = rec >> 2, ks = rec & 3;
    int g = lane >> 2, tig = lane & 3;
    int n = (ntp * 2 + (sub >> 2)) * 8 + g;
    int k = ks * 16 + ((sub >> 1) & 1) * 8 + 2 * tig + (sub & 1);
    const float* W; int k0;
    if (ci < 4)       { W = We1; k0 = ci * 64; }
    else if (ci < 6)  { W = We2; k0 = (ci - 4) * 64; }
    else if (ci < 8)  { W = Wc1; k0 = (ci - 6) * 64; }
    else if (ci < 12) { W = Wn1; k0 = (ci - 8) * 64; }
    else              { W = Wn2; k0 = (ci - 12) * 64; }
    g_wimg16[ci * 8192 + rec * 256 + slot_of(lane) * 8 + sub] =
        __float2half(W[(k0 + k) * DD + n]);
}

// ---------------- mma cores: warp tile = 2 etiles x FULL 128 n ----------------
// Layer-1 (A from smem chunk, K=64): per ks: 2 A-LDS + 8 B-LDS + 32 mma.
__device__ __forceinline__ void mma_l1(float (&C)[2][16][4], uint32_t xa0, uint32_t xa1,
                                       uint32_t wimg_u, uint32_t slot16) {
#pragma unroll
    for (int ks = 0; ks < 4; ks++) {
        uint4 a0 = lds128(xa0 + (uint32_t)(ks << 9) + slot16);
        uint4 a1 = lds128(xa1 + (uint32_t)(ks << 9) + slot16);
#pragma unroll
        for (int ntp = 0; ntp < 8; ntp++) {
            uint4 b = lds128(wimg_u + (uint32_t)(((ntp * 4 + ks) << 9)) + slot16);
            mma16(C[0][2 * ntp],     a0, b.x, b.y);
            mma16(C[0][2 * ntp + 1], a0, b.z, b.w);
            mma16(C[1][2 * ntp],     a1, b.x, b.y);
            mma16(C[1][2 * ntp + 1], a1, b.z, b.w);
        }
    }
}

// Layers 2/3 (A register-resident, K=128 over two prestaged W ring slots).
__device__ __forceinline__ void mma_reg(float (&C)[2][16][4], uint4 (&A)[2][8],
                                        uint32_t wb0, uint32_t slot16) {
#pragma unroll
    for (int ks = 0; ks < 8; ks++) {
        uint32_t wimg = wb0 + (uint32_t)((ks >> 2) * 16384);
        int ksl = ks & 3;
#pragma unroll
        for (int ntp = 0; ntp < 8; ntp++) {
            uint4 b = lds128(wimg + (uint32_t)(((ntp * 4 + ksl) << 9)) + slot16);
            mma16(C[0][2 * ntp],     A[0][ks], b.x, b.y);
            mma16(C[0][2 * ntp + 1], A[0][ks], b.z, b.w);
            mma16(C[1][2 * ntp],     A[1][ks], b.x, b.y);
            mma16(C[1][2 * ntp + 1], A[1][ks], b.z, b.w);
        }
    }
}

// Stage one 16KB W chunk (128 threads, 8 x cp.async.16 each).
__device__ __forceinline__ void stageW(uint32_t wbuf_u, const __half* __restrict__ img, int t) {
#pragma unroll
    for (int i = 0; i < 8; i++)
        CP_ASYNC_16(wbuf_u + (uint32_t)((i * 128 + t) * 16), (const char*)(img + (i * 128 + t) * 8));
}

// Gather one K=64 fp16 chunk for warp w's 2 etiles (lane-local slots).
__device__ __forceinline__ void gatherX(uint32_t xbuf_u, int c, int w, int g, int tig,
                                        uint32_t slot16, const __half* __restrict__ hb,
                                        const int* srow, const int* scol) {
#pragma unroll
    for (int mtl = 0; mtl < 2; mtl++) {
        int etile = 2 * w + mtl;
        int nlo = (c < 2 ? srow : scol)[etile * 16 + g];
        int nhi = (c < 2 ? srow : scol)[etile * 16 + g + 8];
        const __half* slo = hb + (long long)nlo * DD + (c & 1) * 64 + 2 * tig;
        const __half* shi = hb + (long long)nhi * DD + (c & 1) * 64 + 2 * tig;
#pragma unroll
        for (int ks = 0; ks < 4; ks++) {
            uint32_t rec = xbuf_u + (uint32_t)(((etile * 4 + ks) << 9)) + slot16;
            CP_ASYNC_4(rec + 0,  (const char*)(slo + ks * 16));
            CP_ASYNC_4(rec + 4,  (const char*)(shi + ks * 16));
            CP_ASYNC_4(rec + 8,  (const char*)(slo + ks * 16 + 8));
            CP_ASYNC_4(rec + 12, (const char*)(shi + ks * 16 + 8));
        }
    }
}

__device__ __forceinline__ void gatherN(uint32_t xbuf_u, const __half* __restrict__ hb,
                                        long long n0, long long Nn, int w, int g, int tig,
                                        uint32_t slot16) {
#pragma unroll
    for (int mtl = 0; mtl < 2; mtl++) {
        int etile = 2 * w + mtl;
        long long rlo = n0 + etile * 16 + g;     if (rlo >= Nn) rlo = Nn - 1;
        long long rhi = n0 + etile * 16 + g + 8; if (rhi >= Nn) rhi = Nn - 1;
        const __half* slo = hb + rlo * DD + 2 * tig;
        const __half* shi = hb + rhi * DD + 2 * tig;
#pragma unroll
        for (int ks = 0; ks < 4; ks++) {
            uint32_t rec = xbuf_u + (uint32_t)(((etile * 4 + ks) << 9)) + slot16;
            CP_ASYNC_4(rec + 0,  (const char*)(slo + ks * 16));
            CP_ASYNC_4(rec + 4,  (const char*)(shi + ks * 16));
            CP_ASYNC_4(rec + 8,  (const char*)(slo + ks * 16 + 8));
            CP_ASYNC_4(rec + 12, (const char*)(shi + ks * 16 + 8));
        }
    }
}

#define CLEAR_C() \
    _Pragma("unroll") for (int mt = 0; mt < 2; mt++) \
    _Pragma("unroll") for (int nt = 0; nt < 16; nt++) \
    _Pragma("unroll") for (int q = 0; q < 4; q++) C[mt][nt][q] = 0.0f

// ================= edge kernel =================
__global__ __launch_bounds__(128, 2) void egnn_edge_mma(
    const float* __restrict__ pos, const int* __restrict__ ei32, long long E,
    const float* __restrict__ We1, const float* __restrict__ be1,
    const float* __restrict__ be2, const float* __restrict__ bc1,
    const float* __restrict__ Wc2, float* __restrict__ pos_out)
{
    extern __shared__ __align__(16) float smem[];
    char* sb = (char*)smem;
    const uint32_t sbase = smem_u32(smem);
    __half* xh   = (__half*)(sb + XB_B);
    int*   srow  = (int*)(sb + SROW_B);
    int*   scol  = (int*)(sb + SCOL_B);
    float* sdx   = (float*)(sb + SDX_B);
    float* sdy   = (float*)(sb + SDY_B);
    float* sdz   = (float*)(sb + SDZ_B);
    float* sid   = (float*)(sb + SID_B);
    float* sdist = (float*)(sb + SDIST_B);
    float* w257s = (float*)(sb + W257_B);
    float* swc2  = (float*)(sb + SWC2_B);
    float* sbe1  = (float*)(sb + SBE1_B);
    float* sbe2  = (float*)(sb + SBE2_B);
    float* sbc1  = (float*)(sb + SBC1_B);

    const int t = threadIdx.x;
    const int w = t >> 5;
    const int lane = t & 31;
    const int g = lane >> 2;
    const int tig = lane & 3;
    const int e0t = 2 * w;
    const uint32_t slot16 = (uint32_t)(slot_of(lane) * 16);
    const long long e0 = (long long)blockIdx.x * EPB;

    {   // edge meta + tables (one edge per thread; t covers 0..127)
        long long e = e0 + t;
        if (e >= E) e = E - 1;
        int r, c;
        if (g_is64) { r = ei32[2 * e]; c = ei32[2 * (E + e)]; }
        else        { r = ei32[e];     c = ei32[E + e]; }
        srow[t] = r; scol[t] = c;
        float dx = pos[r * 3 + 0] - pos[c * 3 + 0];
        float dy = pos[r * 3 + 1] - pos[c * 3 + 1];
        float dz = pos[r * 3 + 2] - pos[c * 3 + 2];
        float d = sqrtf(dx * dx + dy * dy + dz * dz);
        d = fmaxf(d, 1e-6f);
        sdx[t] = dx; sdy[t] = dy; sdz[t] = dz;
        sid[t] = 1.0f / d; sdist[t] = d;
        w257s[t] = We1[256 * DD + t];
        swc2[t]  = Wc2[t];
        sbe1[t]  = be1[t];
        sbe2[t]  = be2[t];
        sbc1[t]  = bc1[t];
    }
    __syncthreads();

    float C[2][16][4];
    uint4 Af[2][8];          // next-layer A fragments (reused for layers 2 and 3)
    const uint32_t xb0 = sbase + XB_B;
    const uint32_t wb0 = sbase + WB_B;

    // ---------- layer 1: K=256, 4 pipelined K=64 chunks ----------
    CLEAR_C();
    stageW(wb0, g_wimg16 + 0 * 8192, t);
    gatherX(xb0, 0, w, g, tig, slot16, g_h16, srow, scol);
    CP_COMMIT();
    stageW(wb0 + 16384, g_wimg16 + 1 * 8192, t);
    gatherX(xb0 + 16384, 1, w, g, tig, slot16, g_h16, srow, scol);
    CP_COMMIT();

#pragma unroll
    for (int c = 0; c < 4; c++) {
        if (c < 3) CP_WAIT(1); else CP_WAIT(0);
        __syncthreads();
        uint32_t bx = xb0 + (uint32_t)((c & 1) * 16384);
        mma_l1(C, bx + (uint32_t)((e0t * 4) << 9), bx + (uint32_t)(((e0t + 1) * 4) << 9),
               wb0 + (uint32_t)((c & 1) * 16384), slot16);
        __syncthreads();
        if (c < 2) {
            stageW(wb0 + (uint32_t)((c & 1) * 16384), g_wimg16 + (c + 2) * 8192, t);
            gatherX(xb0 + (uint32_t)((c & 1) * 16384), c + 2, w, g, tig, slot16,
                    g_h16, srow, scol);
            CP_COMMIT();
        }
    }

    // stage BOTH layer-2 W chunks
    stageW(wb0, g_wimg16 + 4 * 8192, t);
    stageW(wb0 + 16384, g_wimg16 + 5 * 8192, t);
    CP_COMMIT();

    // epilogue 1: + dist*w257 + be1, silu -> Af (REGISTERS ONLY, no smem)
#pragma unroll
    for (int mt = 0; mt < 2; mt++) {
        int etile = e0t + mt;
        float dlo = sdist[etile * 16 + g];
        float dhi = sdist[etile * 16 + g + 8];
#pragma unroll
        for (int l = 0; l < 8; l++) {
            int nt0 = 2 * l, nt1 = nt0 + 1;
            int n00 = nt0 * 8 + 2 * tig, n01 = n00 + 1;
            int n10 = nt1 * 8 + 2 * tig, n11 = n10 + 1;
            float w00 = w257s[n00], w01 = w257s[n01], w10 = w257s[n10], w11 = w257s[n11];
            float b00 = sbe1[n00], b01 = sbe1[n01], b10 = sbe1[n10], b11 = sbe1[n11];
            uint4 v;
            v.x = h2u(silu_f(C[mt][nt0][0] + dlo * w00 + b00), silu_f(C[mt][nt0][1] + dlo * w01 + b01));
            v.y = h2u(silu_f(C[mt][nt0][2] + dhi * w00 + b00), silu_f(C[mt][nt0][3] + dhi * w01 + b01));
            v.z = h2u(silu_f(C[mt][nt1][0] + dlo * w10 + b10), silu_f(C[mt][nt1][1] + dlo * w11 + b11));
            v.w = h2u(silu_f(C[mt][nt1][2] + dhi * w10 + b10), silu_f(C[mt][nt1][3] + dhi * w11 + b11));
            Af[mt][l] = v;
        }
    }
    CP_WAIT(0);
    __syncthreads();   // layer-2 weights visible

    // ---------- layer 2: K=128, A register-resident ----------
    CLEAR_C();
    mma_reg(C, Af, wb0, slot16);
    __syncthreads();   // all warps done reading layer-2 W

    stageW(wb0, g_wimg16 + 6 * 8192, t);
    stageW(wb0 + 16384, g_wimg16 + 7 * 8192, t);
    CP_COMMIT();

    // epilogue 2: msg = silu(C + be2) -> Af (regs) + X3 smem copy for the agg scatter
#pragma unroll
    for (int mt = 0; mt < 2; mt++) {
        int etile = e0t + mt;
#pragma unroll
        for (int l = 0; l < 8; l++) {
            int nt0 = 2 * l, nt1 = nt0 + 1;
            int n00 = nt0 * 8 + 2 * tig, n01 = n00 + 1;
            int n10 = nt1 * 8 + 2 * tig, n11 = n10 + 1;
            float b00 = sbe2[n00], b01 = sbe2[n01], b10 = sbe2[n10], b11 = sbe2[n11];
            uint4 v;
            v.x = h2u(silu_f(C[mt][nt0][0] + b00), silu_f(C[mt][nt0][1] + b01));
            v.y = h2u(silu_f(C[mt][nt0][2] + b00), silu_f(C[mt][nt0][3] + b01));
            v.z = h2u(silu_f(C[mt][nt1][0] + b10), silu_f(C[mt][nt1][1] + b11));
            v.w = h2u(silu_f(C[mt][nt1][2] + b10), silu_f(C[mt][nt1][3] + b11));
            Af[mt][l] = v;
            sts128(xb0 + (uint32_t)(((etile * 8 + l) << 9)) + slot16, v);
        }
    }
    CP_WAIT(0);
    __syncthreads();   // X3 + layer-3 weights visible

    // ---------- layer 3: K=128, A register-resident ----------
    CLEAR_C();
    mma_reg(C, Af, wb0, slot16);

    // agg scatter from X3 (128 threads; thread t = feature j, all 128 edges)
    {
        int j = t;
        int ks2 = j >> 4, kcol = j & 15;
        int tigp = (kcol & 7) >> 1, jp = kcol & 1;
        int regp = (kcol >> 3) * 2;
        int offs[16];
#pragma unroll
        for (int r = 0; r < 16; r++) {
            int lanep = (r & 7) * 4 + tigp;
            offs[r] = ks2 * 256 + slot_of(lanep) * 8 + (regp + (r >> 3)) * 2 + jp;
        }
        float* aggj = g_agg + j;
        if (e0 + EPB <= E) {
#pragma unroll 2
            for (int eq = 0; eq < 8; eq++) {
                int base16 = eq * 2048;
                int ewb = eq * 16;
#pragma unroll
                for (int r = 0; r < 16; r++) {
                    float m = __half2float(xh[base16 + offs[r]]);
                    atomicAdd(aggj + (long long)srow[ewb + r] * DD, m);
                }
            }
        } else {
#pragma unroll 2
            for (int ew = 0; ew < 128; ew++) {
                if (e0 + ew < E) {
                    float m = __half2float(xh[(ew >> 4) * 2048 + offs[ew & 15]]);
                    atomicAdd(aggj + (long long)srow[ew] * DD, m);
                }
            }
        }
    }

    // coord epilogue: warp owns full n -> warp-local reduce, direct pos atomics
    {
        float sp[2][2] = {{0.f, 0.f}, {0.f, 0.f}};
#pragma unroll
        for (int mt = 0; mt < 2; mt++)
#pragma unroll
            for (int nt = 0; nt < 16; nt++)
#pragma unroll
                for (int q = 0; q < 4; q++) {
                    int n = nt * 8 + 2 * tig + (q & 1);
                    sp[mt][q >> 1] += silu_f(C[mt][nt][q] + sbc1[n]) * swc2[n];
                }
#pragma unroll
        for (int mt = 0; mt < 2; mt++)
#pragma unroll
            for (int hb = 0; hb < 2; hb++) {
                float s = sp[mt][hb];
                s += __shfl_xor_sync(0xFFFFFFFFu, s, 1);
                s += __shfl_xor_sync(0xFFFFFFFFu, s, 2);
                sp[mt][hb] = s;
            }
        if (tig == 0) {
#pragma unroll
            for (int mt = 0; mt < 2; mt++)
#pragma unroll
                for (int hb = 0; hb < 2; hb++) {
                    int ew = (e0t + mt) * 16 + g + 8 * hb;
                    if (e0 + ew < E) {
                        float s = fminf(fmaxf(sp[mt][hb], -1.0f), 1.0f);
                        float fac = s * sid[ew];
                        long long rr = srow[ew];
                        atomicAdd(&pos_out[rr * 3 + 0], sdx[ew] * fac);
                        atomicAdd(&pos_out[rr * 3 + 1], sdy[ew] * fac);
                        atomicAdd(&pos_out[rr * 3 + 2], sdz[ew] * fac);
                    }
                }
        }
    }
}

// ================= node kernel =================
__global__ __launch_bounds__(128, 2) void egnn_node_mma(
    const float* __restrict__ h,
    const float* __restrict__ bn1, const float* __restrict__ bn2,
    float* __restrict__ h_out, long long N)
{
    extern __shared__ __align__(16) float smem[];
    char* sb = (char*)smem;
    const uint32_t sbase = smem_u32(smem);
    float* sbn1 = (float*)(sb + NBN1_B);
    float* sbn2 = (float*)(sb + NBN2_B);

    const int t = threadIdx.x;
    const int w = t >> 5;
    const int lane = t & 31;
    const int g = lane >> 2;
    const int tig = lane & 3;
    const int e0t = 2 * w;
    const uint32_t slot16 = (uint32_t)(slot_of(lane) * 16);
    const long long n0 = (long long)blockIdx.x * EPB;

    sbn1[t] = bn1[t];
    sbn2[t] = bn2[t];
    __syncthreads();

    float C[2][16][4];
    uint4 Af[2][8];
    const uint32_t xb0 = sbase + XB_B;
    const uint32_t wb0 = sbase + NWB_B;

    // layer A: K=256 ([h16 ; agg16]), 4 pipelined chunks
    CLEAR_C();
    stageW(wb0, g_wimg16 + 8 * 8192, t);
    gatherN(xb0, g_h16, n0, N, w, g, tig, slot16);
    CP_COMMIT();
    stageW(wb0 + 16384, g_wimg16 + 9 * 8192, t);
    gatherN(xb0 + 16384, g_h16 + 64, n0, N, w, g, tig, slot16);
    CP_COMMIT();

#pragma unroll
    for (int c = 0; c < 4; c++) {
        if (c < 3) CP_WAIT(1); else CP_WAIT(0);
        __syncthreads();
        uint32_t bx = xb0 + (uint32_t)((c & 1) * 16384);
        mma_l1(C, bx + (uint32_t)((e0t * 4) << 9), bx + (uint32_t)(((e0t + 1) * 4) << 9),
               wb0 + (uint32_t)((c & 1) * 16384), slot16);
        __syncthreads();
        if (c < 2) {
            const __half* base = g_agg16 + (c & 1) * 64;
            stageW(wb0 + (uint32_t)((c & 1) * 16384), g_wimg16 + (10 + c) * 8192, t);
            gatherN(xb0 + (uint32_t)((c & 1) * 16384), base, n0, N, w, g, tig, slot16);
            CP_COMMIT();
        }
    }

    stageW(wb0, g_wimg16 + 12 * 8192, t);
    stageW(wb0 + 16384, g_wimg16 + 13 * 8192, t);
    CP_COMMIT();

    // epilogue A: silu(C + bn1) -> Af (registers only)
#pragma unroll
    for (int mt = 0; mt < 2; mt++) {
#pragma unroll
        for (int l = 0; l < 8; l++) {
            int nt0 = 2 * l, nt1 = nt0 + 1;
            int n00 = nt0 * 8 + 2 * tig, n01 = n00 + 1;
            int n10 = nt1 * 8 + 2 * tig, n11 = n10 + 1;
            float b00 = sbn1[n00], b01 = sbn1[n01], b10 = sbn1[n10], b11 = sbn1[n11];
            uint4 v;
            v.x = h2u(silu_f(C[mt][nt0][0] + b00), silu_f(C[mt][nt0][1] + b01));
            v.y = h2u(silu_f(C[mt][nt0][2] + b00), silu_f(C[mt][nt0][3] + b01));
            v.z = h2u(silu_f(C[mt][nt1][0] + b10), silu_f(C[mt][nt1][1] + b11));
            v.w = h2u(silu_f(C[mt][nt1][2] + b10), silu_f(C[mt][nt1][3] + b11));
            Af[mt][l] = v;
        }
    }
    CP_WAIT(0);
    __syncthreads();

    // layer B: K=128, A register-resident
    CLEAR_C();
    mma_reg(C, Af, wb0, slot16);

    // epilogue B: h_out = h + C + bn2 (direct float2 gmem)
#pragma unroll
    for (int mt = 0; mt < 2; mt++) {
        int etile = e0t + mt;
#pragma unroll
        for (int nt = 0; nt < 16; nt++) {
            int n = nt * 8 + 2 * tig;
            float b0 = sbn2[n], b1 = sbn2[n + 1];
#pragma unroll
            for (int qh = 0; qh < 2; qh++) {
                long long node = n0 + etile * 16 + g + 8 * qh;
                if (node < N) {
                    float2 hv = *reinterpret_cast<const float2*>(h + node * DD + n);
                    float2 o;
                    o.x = hv.x + C[mt][nt][2 * qh + 0] + b0;
                    o.y = hv.y + C[mt][nt][2 * qh + 1] + b1;
                    *reinterpret_cast<float2*>(h_out + node * DD + n) = o;
                }
            }
        }
    }
}

// ---------------- launcher ----------------
extern "C" void kernel_launch(void* const* d_in, const int* in_sizes, int n_in,
                              void* d_out, int out_size)
{
    const float* h   = (const float*)d_in[0];
    const float* pos = (const float*)d_in[1];
    const int*   ei  = (const int*)d_in[2];
    const float* We1 = (const float*)d_in[3];
    const float* be1 = (const float*)d_in[4];
    const float* We2 = (const float*)d_in[5];
    const float* be2 = (const float*)d_in[6];
    const float* Wn1 = (const float*)d_in[7];
    const float* bn1 = (const float*)d_in[8];
    const float* Wn2 = (const float*)d_in[9];
    const float* bn2 = (const float*)d_in[10];
    const float* Wc1 = (const float*)d_in[11];
    const float* bc1 = (const float*)d_in[12];
    const float* Wc2 = (const float*)d_in[13];

    const long long N = in_sizes[0] / DD;
    const long long E = (long long)in_sizes[2] / 2;

    float* h_out   = (float*)d_out;
    float* pos_out = h_out + N * DD;

    cudaFuncSetAttribute(egnn_edge_mma, cudaFuncAttributeMaxDynamicSharedMemorySize, EDGE_SMEM_BYTES);
    cudaFuncSetAttribute(egnn_node_mma, cudaFuncAttributeMaxDynamicSharedMemorySize, NODE_SMEM_BYTES);

    egnn_detect_kernel<<<1, 1>>>(ei);
    egnn_prep_w<<<(14 * 8192 + 255) / 256, 256>>>(We1, We2, Wc1, Wn1, Wn2);

    long long nAgg = N * DD;
    long long nPos = N * 3;
    egnn_init_kernel<<<(int)((nAgg + 255) / 256), 256>>>(pos, h, pos_out, nAgg, nPos);

    int eb = (int)((E + EPB - 1) / EPB);
    egnn_edge_mma<<<eb, 128, EDGE_SMEM_BYTES>>>(
        pos, ei, E, We1, be1, be2, bc1, Wc2, pos_out);

    egnn_conv_agg<<<(int)((nAgg + 255) / 256), 256>>>(nAgg);

    int nb = (int)((N + EPB - 1) / EPB);
    egnn_node_mma<<<nb, 128, NODE_SMEM_BYTES>>>(
        h, bn1, bn2, h_out, N);
}